// round 1
// baseline (speedup 1.0000x reference)
#include <cuda_runtime.h>
#include <cuda_bf16.h>
#include <cstddef>

// Problem constants
constexpr int B  = 4;
constexpr int S  = 1024;
constexpr int D  = 1024;
constexpr int H  = 16;
constexpr int DK = 64;
constexpr int M  = B * S;          // 4096 rows for projections

// Scratch (device globals: allocation-free per harness rules)
__device__ float d_Q[(size_t)M * D];
__device__ float d_K[(size_t)M * D];
__device__ float d_V[(size_t)M * D];
__device__ float d_Scores[(size_t)B * H * S * S];   // 256 MB
__device__ float d_Xt[(size_t)M * D];
__device__ float d_wmean[D];
__device__ float d_bmean;

// ---------------------------------------------------------------------------
// Projection GEMM: C[m,n] = sum_k A[m,k] * W[n,k] + bias[n]
// M=4096, N=1024, K=1024.  128x128 block, BK=16, 256 threads, 8x8 per thread.
// ---------------------------------------------------------------------------
__global__ __launch_bounds__(256) void gemm_bias_kernel(
    const float* __restrict__ A, const float* __restrict__ W,
    const float* __restrict__ bias, float* __restrict__ C)
{
    __shared__ float As[16][128];
    __shared__ float Ws[16][128];

    const int t  = threadIdx.x;
    const int m0 = blockIdx.y * 128;
    const int n0 = blockIdx.x * 128;
    const int tx = t % 16;          // col group (8 cols)
    const int ty = t / 16;          // row group (8 rows)

    float acc[8][8] = {};

    for (int k0 = 0; k0 < D; k0 += 16) {
        // Load A tile (128 rows x 16 k), transposed into As[k][m]
        #pragma unroll
        for (int e = t; e < 512; e += 256) {
            int row = e >> 2;
            int kc  = (e & 3) << 2;
            float4 v = *(const float4*)(A + (size_t)(m0 + row) * D + k0 + kc);
            As[kc + 0][row] = v.x; As[kc + 1][row] = v.y;
            As[kc + 2][row] = v.z; As[kc + 3][row] = v.w;
        }
        // Load W tile (128 n-rows x 16 k), transposed into Ws[k][n]
        #pragma unroll
        for (int e = t; e < 512; e += 256) {
            int row = e >> 2;
            int kc  = (e & 3) << 2;
            float4 v = *(const float4*)(W + (size_t)(n0 + row) * D + k0 + kc);
            Ws[kc + 0][row] = v.x; Ws[kc + 1][row] = v.y;
            Ws[kc + 2][row] = v.z; Ws[kc + 3][row] = v.w;
        }
        __syncthreads();

        #pragma unroll
        for (int kk = 0; kk < 16; kk++) {
            float a[8], b[8];
            #pragma unroll
            for (int i = 0; i < 8; i++) a[i] = As[kk][ty * 8 + i];
            #pragma unroll
            for (int j = 0; j < 8; j++) b[j] = Ws[kk][tx * 8 + j];
            #pragma unroll
            for (int i = 0; i < 8; i++)
                #pragma unroll
                for (int j = 0; j < 8; j++)
                    acc[i][j] += a[i] * b[j];
        }
        __syncthreads();
    }

    #pragma unroll
    for (int i = 0; i < 8; i++) {
        int m = m0 + ty * 8 + i;
        #pragma unroll
        for (int j = 0; j < 8; j++) {
            int n = n0 + tx * 8 + j;
            C[(size_t)m * D + n] = acc[i][j] + bias[n];
        }
    }
}

// ---------------------------------------------------------------------------
// Scores: S[bh,q,k] = (Q_bh . K_bh) / 8, masked.  Per bh: M=N=1024, K=64.
// ---------------------------------------------------------------------------
__global__ __launch_bounds__(256) void scores_kernel(const int* __restrict__ mask)
{
    __shared__ float As[16][128];
    __shared__ float Bs[16][128];

    const int bh = blockIdx.z;
    const int b  = bh >> 4;
    const int h  = bh & 15;
    const float* Qb = d_Q + (size_t)b * S * D + h * DK;   // row stride D
    const float* Kb = d_K + (size_t)b * S * D + h * DK;

    const int t  = threadIdx.x;
    const int m0 = blockIdx.y * 128;
    const int n0 = blockIdx.x * 128;
    const int tx = t % 16;
    const int ty = t / 16;

    float acc[8][8] = {};

    for (int k0 = 0; k0 < DK; k0 += 16) {
        #pragma unroll
        for (int e = t; e < 512; e += 256) {
            int row = e >> 2;
            int kc  = (e & 3) << 2;
            float4 v = *(const float4*)(Qb + (size_t)(m0 + row) * D + k0 + kc);
            As[kc + 0][row] = v.x; As[kc + 1][row] = v.y;
            As[kc + 2][row] = v.z; As[kc + 3][row] = v.w;
        }
        #pragma unroll
        for (int e = t; e < 512; e += 256) {
            int row = e >> 2;
            int kc  = (e & 3) << 2;
            float4 v = *(const float4*)(Kb + (size_t)(n0 + row) * D + k0 + kc);
            Bs[kc + 0][row] = v.x; Bs[kc + 1][row] = v.y;
            Bs[kc + 2][row] = v.z; Bs[kc + 3][row] = v.w;
        }
        __syncthreads();

        #pragma unroll
        for (int kk = 0; kk < 16; kk++) {
            float a[8], bb[8];
            #pragma unroll
            for (int i = 0; i < 8; i++) a[i] = As[kk][ty * 8 + i];
            #pragma unroll
            for (int j = 0; j < 8; j++) bb[j] = Bs[kk][tx * 8 + j];
            #pragma unroll
            for (int i = 0; i < 8; i++)
                #pragma unroll
                for (int j = 0; j < 8; j++)
                    acc[i][j] += a[i] * bb[j];
        }
        __syncthreads();
    }

    float* Sb = d_Scores + (size_t)bh * S * S;
    const int* mb = mask + (size_t)b * S * S;
    #pragma unroll
    for (int i = 0; i < 8; i++) {
        int m = m0 + ty * 8 + i;
        #pragma unroll
        for (int j = 0; j < 8; j++) {
            int n = n0 + tx * 8 + j;
            float v = acc[i][j] * 0.125f;
            if (mb[(size_t)m * S + n] == 0) v = -1e9f;
            Sb[(size_t)m * S + n] = v;
        }
    }
}

// ---------------------------------------------------------------------------
// Row softmax over 1024 elements, in place. One block per row, 256 threads.
// ---------------------------------------------------------------------------
__global__ __launch_bounds__(256) void softmax_kernel()
{
    __shared__ float red[8];
    __shared__ float bc;

    const size_t row = blockIdx.x;
    float* p = d_Scores + row * S;
    const int t = threadIdx.x;

    float4 v = *(const float4*)(p + t * 4);
    float mx = fmaxf(fmaxf(v.x, v.y), fmaxf(v.z, v.w));
    #pragma unroll
    for (int o = 16; o > 0; o >>= 1)
        mx = fmaxf(mx, __shfl_xor_sync(0xffffffffu, mx, o));
    if ((t & 31) == 0) red[t >> 5] = mx;
    __syncthreads();
    if (t < 8) {
        float m = red[t];
        #pragma unroll
        for (int o = 4; o > 0; o >>= 1)
            m = fmaxf(m, __shfl_xor_sync(0xffu, m, o));
        if (t == 0) bc = m;
    }
    __syncthreads();
    mx = bc;

    float4 e;
    e.x = __expf(v.x - mx); e.y = __expf(v.y - mx);
    e.z = __expf(v.z - mx); e.w = __expf(v.w - mx);
    float sum = e.x + e.y + e.z + e.w;
    #pragma unroll
    for (int o = 16; o > 0; o >>= 1)
        sum += __shfl_xor_sync(0xffffffffu, sum, o);
    if ((t & 31) == 0) red[t >> 5] = sum;
    __syncthreads();
    if (t < 8) {
        float s = red[t];
        #pragma unroll
        for (int o = 4; o > 0; o >>= 1)
            s += __shfl_xor_sync(0xffu, s, o);
        if (t == 0) bc = s;
    }
    __syncthreads();
    float inv = 1.0f / bc;

    e.x *= inv; e.y *= inv; e.z *= inv; e.w *= inv;
    *(float4*)(p + t * 4) = e;
}

// ---------------------------------------------------------------------------
// PV: X[bh,q,:] = P @ V_bh, with threshold epilogue, written to [b,s,h*DK+dk].
// Per bh: M=1024, N=64, K=1024. Block: 128x64, BK=16, 256 threads, 8x4/thread.
// ---------------------------------------------------------------------------
__global__ __launch_bounds__(256) void pv_kernel()
{
    __shared__ float Ps[16][128];
    __shared__ float Vs[16][64];

    const int bh = blockIdx.z;
    const int b  = bh >> 4;
    const int h  = bh & 15;
    const float* P  = d_Scores + (size_t)bh * S * S;
    const float* Vb = d_V + (size_t)b * S * D + h * DK;

    const int t  = threadIdx.x;
    const int m0 = blockIdx.y * 128;
    const int tx = t % 16;          // 16 col groups x 4 = 64
    const int ty = t / 16;          // 16 row groups x 8 = 128

    float acc[8][4] = {};

    for (int k0 = 0; k0 < S; k0 += 16) {
        #pragma unroll
        for (int e = t; e < 512; e += 256) {
            int row = e >> 2;
            int kc  = (e & 3) << 2;
            float4 v = *(const float4*)(P + (size_t)(m0 + row) * S + k0 + kc);
            Ps[kc + 0][row] = v.x; Ps[kc + 1][row] = v.y;
            Ps[kc + 2][row] = v.z; Ps[kc + 3][row] = v.w;
        }
        {
            int row = t / 16;       // 0..15 (k within tile)
            int c   = (t % 16) * 4; // 0..60
            float4 v = *(const float4*)(Vb + (size_t)(k0 + row) * D + c);
            Vs[row][c + 0] = v.x; Vs[row][c + 1] = v.y;
            Vs[row][c + 2] = v.z; Vs[row][c + 3] = v.w;
        }
        __syncthreads();

        #pragma unroll
        for (int kk = 0; kk < 16; kk++) {
            float a[8], bv[4];
            #pragma unroll
            for (int i = 0; i < 8; i++) a[i] = Ps[kk][ty * 8 + i];
            #pragma unroll
            for (int j = 0; j < 4; j++) bv[j] = Vs[kk][tx * 4 + j];
            #pragma unroll
            for (int i = 0; i < 8; i++)
                #pragma unroll
                for (int j = 0; j < 4; j++)
                    acc[i][j] += a[i] * bv[j];
        }
        __syncthreads();
    }

    #pragma unroll
    for (int i = 0; i < 8; i++) {
        int m = m0 + ty * 8 + i;
        #pragma unroll
        for (int j = 0; j < 4; j++) {
            int n = tx * 4 + j;
            float v = acc[i][j];
            v = (v > 0.2f) ? v : 0.0f;     // F.threshold(x, 0.2, 0.0)
            d_Xt[(size_t)(b * S + m) * D + h * DK + n] = v;
        }
    }
}

// ---------------------------------------------------------------------------
// Column means of Wo (and mean of bo): wmean[k] = mean_n Wo[n,k]
// ---------------------------------------------------------------------------
__global__ __launch_bounds__(256) void wmean_kernel(const float* __restrict__ Wo,
                                                    const float* __restrict__ bo)
{
    int k = blockIdx.x * 256 + threadIdx.x;
    float s = 0.0f;
    for (int n = 0; n < D; n++) s += Wo[(size_t)n * D + k];
    d_wmean[k] = s * (1.0f / D);
    if (k == 0) {
        float sb = 0.0f;
        for (int n = 0; n < D; n++) sb += bo[n];
        d_bmean = sb * (1.0f / D);
    }
}

// ---------------------------------------------------------------------------
// Final: out[r,:] = Xt[r,:] + (Xt[r,:] . wmean + bmean)
// One block (256 threads) per row.
// ---------------------------------------------------------------------------
__global__ __launch_bounds__(256) void final_kernel(float* __restrict__ out)
{
    __shared__ float red[8];
    __shared__ float bc;

    const size_t row = blockIdx.x;
    const float* x = d_Xt + row * D;
    const int t = threadIdx.x;

    float partial = 0.0f;
    #pragma unroll
    for (int dd = 0; dd < 4; dd++) {
        int idx = t + dd * 256;
        partial += x[idx] * d_wmean[idx];
    }
    #pragma unroll
    for (int o = 16; o > 0; o >>= 1)
        partial += __shfl_xor_sync(0xffffffffu, partial, o);
    if ((t & 31) == 0) red[t >> 5] = partial;
    __syncthreads();
    if (t < 8) {
        float s = red[t];
        #pragma unroll
        for (int o = 4; o > 0; o >>= 1)
            s += __shfl_xor_sync(0xffu, s, o);
        if (t == 0) bc = s + d_bmean;
    }
    __syncthreads();
    float scalar = bc;

    #pragma unroll
    for (int dd = 0; dd < 4; dd++) {
        int idx = t + dd * 256;
        out[row * D + idx] = x[idx] + scalar;
    }
}

// ---------------------------------------------------------------------------
extern "C" void kernel_launch(void* const* d_in, const int* in_sizes, int n_in,
                              void* d_out, int out_size)
{
    const float* query = (const float*)d_in[0];
    const float* key_  = (const float*)d_in[1];
    const float* value = (const float*)d_in[2];
    const int*   mask  = (const int*)  d_in[3];
    const float* Wq    = (const float*)d_in[4];
    const float* bq    = (const float*)d_in[5];
    const float* Wk    = (const float*)d_in[6];
    const float* bk    = (const float*)d_in[7];
    const float* Wv    = (const float*)d_in[8];
    const float* bv    = (const float*)d_in[9];
    const float* Wo    = (const float*)d_in[10];
    const float* bo    = (const float*)d_in[11];
    float* out = (float*)d_out;

    float *Qp, *Kp, *Vp;
    cudaGetSymbolAddress((void**)&Qp, d_Q);
    cudaGetSymbolAddress((void**)&Kp, d_K);
    cudaGetSymbolAddress((void**)&Vp, d_V);

    dim3 gproj(D / 128, M / 128);                    // 8 x 32
    gemm_bias_kernel<<<gproj, 256>>>(query, Wq, bq, Qp);
    gemm_bias_kernel<<<gproj, 256>>>(key_,  Wk, bk, Kp);
    gemm_bias_kernel<<<gproj, 256>>>(value, Wv, bv, Vp);

    wmean_kernel<<<D / 256, 256>>>(Wo, bo);          // overlappable, tiny

    dim3 gsc(S / 128, S / 128, B * H);               // 8 x 8 x 64
    scores_kernel<<<gsc, 256>>>(mask);

    softmax_kernel<<<B * H * S, 256>>>();            // 65536 rows

    dim3 gpv(1, S / 128, B * H);                     // 1 x 8 x 64
    pv_kernel<<<gpv, 256>>>();

    final_kernel<<<M, 256>>>(out);
}

// round 2
// speedup vs baseline: 1.0145x; 1.0145x over previous
#include <cuda_runtime.h>
#include <cuda_bf16.h>
#include <cstddef>

// Problem constants
constexpr int B  = 4;
constexpr int S  = 1024;
constexpr int D  = 1024;
constexpr int H  = 16;
constexpr int DK = 64;
constexpr int M  = B * S;          // 4096 rows for projections

// Scratch (device globals: allocation-free per harness rules)
__device__ float d_Q[(size_t)M * D];
__device__ float d_K[(size_t)M * D];
__device__ float d_V[(size_t)M * D];
__device__ float d_Scores[(size_t)B * H * S * S];   // 256 MB
__device__ float d_Xt[(size_t)M * D];
__device__ float d_wmean[D];
__device__ float d_bmean;

// ---------------------------------------------------------------------------
// Packed fp32x2 helpers (sm_100+): FFMA2 = 2 IEEE fp32 FMAs per lane per instr
// ---------------------------------------------------------------------------
__device__ __forceinline__ unsigned long long dup2(float x) {
    unsigned long long r;
    unsigned int u = __float_as_uint(x);
    asm("mov.b64 %0, {%1, %1};" : "=l"(r) : "r"(u));
    return r;
}
__device__ __forceinline__ void ffma2(unsigned long long& d,
                                      unsigned long long a,
                                      unsigned long long b) {
    asm("fma.rn.f32x2 %0, %1, %2, %0;" : "+l"(d) : "l"(a), "l"(b));
}
__device__ __forceinline__ void unpack2(unsigned long long v, float& lo, float& hi) {
    unsigned int ulo, uhi;
    asm("mov.b64 {%0, %1}, %2;" : "=r"(ulo), "=r"(uhi) : "l"(v));
    lo = __uint_as_float(ulo);
    hi = __uint_as_float(uhi);
}

// ---------------------------------------------------------------------------
// Projection GEMM: C[m,n] = sum_k A[m,k] * W[n,k] + bias[n]
// M=4096, N=1024, K=1024.  128x128 block, BK=16, 256 threads, 8x8 per thread.
// Inner loop in fma.rn.f32x2 (acc pairs along n).
// ---------------------------------------------------------------------------
__global__ __launch_bounds__(256, 2) void gemm_bias_kernel(
    const float* __restrict__ A, const float* __restrict__ W,
    const float* __restrict__ bias, float* __restrict__ C)
{
    __shared__ float As[16][128];
    __shared__ float Ws[16][128];

    const int t  = threadIdx.x;
    const int m0 = blockIdx.y * 128;
    const int n0 = blockIdx.x * 128;
    const int tx = t % 16;          // col group (8 cols = 4 pairs)
    const int ty = t / 16;          // row group (8 rows)

    unsigned long long acc2[8][4] = {};   // 8 rows x 4 fp32-pairs

    for (int k0 = 0; k0 < D; k0 += 16) {
        #pragma unroll
        for (int e = t; e < 512; e += 256) {
            int row = e >> 2;
            int kc  = (e & 3) << 2;
            float4 v = *(const float4*)(A + (size_t)(m0 + row) * D + k0 + kc);
            As[kc + 0][row] = v.x; As[kc + 1][row] = v.y;
            As[kc + 2][row] = v.z; As[kc + 3][row] = v.w;
        }
        #pragma unroll
        for (int e = t; e < 512; e += 256) {
            int row = e >> 2;
            int kc  = (e & 3) << 2;
            float4 v = *(const float4*)(W + (size_t)(n0 + row) * D + k0 + kc);
            Ws[kc + 0][row] = v.x; Ws[kc + 1][row] = v.y;
            Ws[kc + 2][row] = v.z; Ws[kc + 3][row] = v.w;
        }
        __syncthreads();

        #pragma unroll
        for (int kk = 0; kk < 16; kk++) {
            float4 a0 = *(const float4*)&As[kk][ty * 8];
            float4 a1 = *(const float4*)&As[kk][ty * 8 + 4];
            ulonglong2 b01 = *(const ulonglong2*)&Ws[kk][tx * 8];
            ulonglong2 b23 = *(const ulonglong2*)&Ws[kk][tx * 8 + 4];
            unsigned long long ad[8] = {
                dup2(a0.x), dup2(a0.y), dup2(a0.z), dup2(a0.w),
                dup2(a1.x), dup2(a1.y), dup2(a1.z), dup2(a1.w)
            };
            unsigned long long bb[4] = { b01.x, b01.y, b23.x, b23.y };
            #pragma unroll
            for (int i = 0; i < 8; i++)
                #pragma unroll
                for (int j = 0; j < 4; j++)
                    ffma2(acc2[i][j], ad[i], bb[j]);
        }
        __syncthreads();
    }

    #pragma unroll
    for (int i = 0; i < 8; i++) {
        int m = m0 + ty * 8 + i;
        #pragma unroll
        for (int j = 0; j < 4; j++) {
            int n = n0 + tx * 8 + 2 * j;
            float lo, hi;
            unpack2(acc2[i][j], lo, hi);
            C[(size_t)m * D + n]     = lo + bias[n];
            C[(size_t)m * D + n + 1] = hi + bias[n + 1];
        }
    }
}

// ---------------------------------------------------------------------------
// Scores: S[bh,q,k] = (Q_bh . K_bh) / 8, masked.  Per bh: M=N=1024, K=64.
// ---------------------------------------------------------------------------
__global__ __launch_bounds__(256, 2) void scores_kernel(const int* __restrict__ mask)
{
    __shared__ float As[16][128];
    __shared__ float Bs[16][128];

    const int bh = blockIdx.z;
    const int b  = bh >> 4;
    const int h  = bh & 15;
    const float* Qb = d_Q + (size_t)b * S * D + h * DK;   // row stride D
    const float* Kb = d_K + (size_t)b * S * D + h * DK;

    const int t  = threadIdx.x;
    const int m0 = blockIdx.y * 128;
    const int n0 = blockIdx.x * 128;
    const int tx = t % 16;
    const int ty = t / 16;

    unsigned long long acc2[8][4] = {};

    for (int k0 = 0; k0 < DK; k0 += 16) {
        #pragma unroll
        for (int e = t; e < 512; e += 256) {
            int row = e >> 2;
            int kc  = (e & 3) << 2;
            float4 v = *(const float4*)(Qb + (size_t)(m0 + row) * D + k0 + kc);
            As[kc + 0][row] = v.x; As[kc + 1][row] = v.y;
            As[kc + 2][row] = v.z; As[kc + 3][row] = v.w;
        }
        #pragma unroll
        for (int e = t; e < 512; e += 256) {
            int row = e >> 2;
            int kc  = (e & 3) << 2;
            float4 v = *(const float4*)(Kb + (size_t)(n0 + row) * D + k0 + kc);
            Bs[kc + 0][row] = v.x; Bs[kc + 1][row] = v.y;
            Bs[kc + 2][row] = v.z; Bs[kc + 3][row] = v.w;
        }
        __syncthreads();

        #pragma unroll
        for (int kk = 0; kk < 16; kk++) {
            float4 a0 = *(const float4*)&As[kk][ty * 8];
            float4 a1 = *(const float4*)&As[kk][ty * 8 + 4];
            ulonglong2 b01 = *(const ulonglong2*)&Bs[kk][tx * 8];
            ulonglong2 b23 = *(const ulonglong2*)&Bs[kk][tx * 8 + 4];
            unsigned long long ad[8] = {
                dup2(a0.x), dup2(a0.y), dup2(a0.z), dup2(a0.w),
                dup2(a1.x), dup2(a1.y), dup2(a1.z), dup2(a1.w)
            };
            unsigned long long bb[4] = { b01.x, b01.y, b23.x, b23.y };
            #pragma unroll
            for (int i = 0; i < 8; i++)
                #pragma unroll
                for (int j = 0; j < 4; j++)
                    ffma2(acc2[i][j], ad[i], bb[j]);
        }
        __syncthreads();
    }

    float* Sb = d_Scores + (size_t)bh * S * S;
    const int* mb = mask + (size_t)b * S * S;
    #pragma unroll
    for (int i = 0; i < 8; i++) {
        int m = m0 + ty * 8 + i;
        #pragma unroll
        for (int j = 0; j < 4; j++) {
            int n = n0 + tx * 8 + 2 * j;
            float lo, hi;
            unpack2(acc2[i][j], lo, hi);
            float v0 = lo * 0.125f;
            float v1 = hi * 0.125f;
            if (mb[(size_t)m * S + n]     == 0) v0 = -1e9f;
            if (mb[(size_t)m * S + n + 1] == 0) v1 = -1e9f;
            Sb[(size_t)m * S + n]     = v0;
            Sb[(size_t)m * S + n + 1] = v1;
        }
    }
}

// ---------------------------------------------------------------------------
// Row softmax over 1024 elements, in place. One block per row, 256 threads.
// ---------------------------------------------------------------------------
__global__ __launch_bounds__(256) void softmax_kernel()
{
    __shared__ float red[8];
    __shared__ float bc;

    const size_t row = blockIdx.x;
    float* p = d_Scores + row * S;
    const int t = threadIdx.x;

    float4 v = *(const float4*)(p + t * 4);
    float mx = fmaxf(fmaxf(v.x, v.y), fmaxf(v.z, v.w));
    #pragma unroll
    for (int o = 16; o > 0; o >>= 1)
        mx = fmaxf(mx, __shfl_xor_sync(0xffffffffu, mx, o));
    if ((t & 31) == 0) red[t >> 5] = mx;
    __syncthreads();
    if (t < 8) {
        float m = red[t];
        #pragma unroll
        for (int o = 4; o > 0; o >>= 1)
            m = fmaxf(m, __shfl_xor_sync(0xffu, m, o));
        if (t == 0) bc = m;
    }
    __syncthreads();
    mx = bc;

    float4 e;
    e.x = __expf(v.x - mx); e.y = __expf(v.y - mx);
    e.z = __expf(v.z - mx); e.w = __expf(v.w - mx);
    float sum = e.x + e.y + e.z + e.w;
    #pragma unroll
    for (int o = 16; o > 0; o >>= 1)
        sum += __shfl_xor_sync(0xffffffffu, sum, o);
    if ((t & 31) == 0) red[t >> 5] = sum;
    __syncthreads();
    if (t < 8) {
        float s = red[t];
        #pragma unroll
        for (int o = 4; o > 0; o >>= 1)
            s += __shfl_xor_sync(0xffu, s, o);
        if (t == 0) bc = s;
    }
    __syncthreads();
    float inv = 1.0f / bc;

    e.x *= inv; e.y *= inv; e.z *= inv; e.w *= inv;
    *(float4*)(p + t * 4) = e;
}

// ---------------------------------------------------------------------------
// PV: X[bh,q,:] = P @ V_bh, with threshold epilogue, written to [b,s,h*DK+dk].
// Per bh: M=1024, N=64, K=1024. Block: 128x64, BK=16, 256 threads, 8x4/thread.
// ---------------------------------------------------------------------------
__global__ __launch_bounds__(256, 2) void pv_kernel()
{
    __shared__ float Ps[16][128];
    __shared__ float Vs[16][64];

    const int bh = blockIdx.z;
    const int b  = bh >> 4;
    const int h  = bh & 15;
    const float* P  = d_Scores + (size_t)bh * S * S;
    const float* Vb = d_V + (size_t)b * S * D + h * DK;

    const int t  = threadIdx.x;
    const int m0 = blockIdx.y * 128;
    const int tx = t % 16;          // 16 col groups x 4 = 64
    const int ty = t / 16;          // 16 row groups x 8 = 128

    unsigned long long acc2[8][2] = {};   // 8 rows x 2 fp32-pairs (4 cols)

    for (int k0 = 0; k0 < S; k0 += 16) {
        #pragma unroll
        for (int e = t; e < 512; e += 256) {
            int row = e >> 2;
            int kc  = (e & 3) << 2;
            float4 v = *(const float4*)(P + (size_t)(m0 + row) * S + k0 + kc);
            Ps[kc + 0][row] = v.x; Ps[kc + 1][row] = v.y;
            Ps[kc + 2][row] = v.z; Ps[kc + 3][row] = v.w;
        }
        {
            int row = t / 16;       // 0..15 (k within tile)
            int c   = (t % 16) * 4; // 0..60
            float4 v = *(const float4*)(Vb + (size_t)(k0 + row) * D + c);
            Vs[row][c + 0] = v.x; Vs[row][c + 1] = v.y;
            Vs[row][c + 2] = v.z; Vs[row][c + 3] = v.w;
        }
        __syncthreads();

        #pragma unroll
        for (int kk = 0; kk < 16; kk++) {
            float4 a0 = *(const float4*)&Ps[kk][ty * 8];
            float4 a1 = *(const float4*)&Ps[kk][ty * 8 + 4];
            ulonglong2 bp = *(const ulonglong2*)&Vs[kk][tx * 4];
            unsigned long long ad[8] = {
                dup2(a0.x), dup2(a0.y), dup2(a0.z), dup2(a0.w),
                dup2(a1.x), dup2(a1.y), dup2(a1.z), dup2(a1.w)
            };
            #pragma unroll
            for (int i = 0; i < 8; i++) {
                ffma2(acc2[i][0], ad[i], bp.x);
                ffma2(acc2[i][1], ad[i], bp.y);
            }
        }
        __syncthreads();
    }

    #pragma unroll
    for (int i = 0; i < 8; i++) {
        int m = m0 + ty * 8 + i;
        #pragma unroll
        for (int j = 0; j < 2; j++) {
            int n = tx * 4 + 2 * j;
            float lo, hi;
            unpack2(acc2[i][j], lo, hi);
            lo = (lo > 0.2f) ? lo : 0.0f;   // F.threshold(x, 0.2, 0.0)
            hi = (hi > 0.2f) ? hi : 0.0f;
            d_Xt[(size_t)(b * S + m) * D + h * DK + n]     = lo;
            d_Xt[(size_t)(b * S + m) * D + h * DK + n + 1] = hi;
        }
    }
}

// ---------------------------------------------------------------------------
// Column means of Wo (and mean of bo): wmean[k] = mean_n Wo[n,k]
// grid = D/32 blocks, 256 threads: 32 cols/block, 8 row-partitions/col.
// ---------------------------------------------------------------------------
__global__ __launch_bounds__(256) void wmean_kernel(const float* __restrict__ Wo,
                                                    const float* __restrict__ bo)
{
    __shared__ float sred[256];

    const int t    = threadIdx.x;
    const int col  = blockIdx.x * 32 + (t & 31);
    const int part = t >> 5;                 // 0..7

    float s = 0.0f;
    const int nlo = part * 128, nhi = nlo + 128;
    for (int n = nlo; n < nhi; n++) s += Wo[(size_t)n * D + col];
    sred[t] = s;
    __syncthreads();

    if (part == 0) {
        float tot = 0.0f;
        #pragma unroll
        for (int p = 0; p < 8; p++) tot += sred[p * 32 + (t & 31)];
        d_wmean[col] = tot * (1.0f / D);
    }
    __syncthreads();

    if (blockIdx.x == 0) {
        float sb = 0.0f;
        #pragma unroll
        for (int i = t; i < D; i += 256) sb += bo[i];
        #pragma unroll
        for (int o = 16; o > 0; o >>= 1)
            sb += __shfl_xor_sync(0xffffffffu, sb, o);
        if ((t & 31) == 0) sred[t >> 5] = sb;
        __syncthreads();
        if (t == 0) {
            float x = 0.0f;
            #pragma unroll
            for (int p = 0; p < 8; p++) x += sred[p];
            d_bmean = x * (1.0f / D);
        }
    }
}

// ---------------------------------------------------------------------------
// Final: out[r,:] = Xt[r,:] + (Xt[r,:] . wmean + bmean)
// One block (256 threads) per row.
// ---------------------------------------------------------------------------
__global__ __launch_bounds__(256) void final_kernel(float* __restrict__ out)
{
    __shared__ float red[8];
    __shared__ float bc;

    const size_t row = blockIdx.x;
    const float* x = d_Xt + row * D;
    const int t = threadIdx.x;

    float partial = 0.0f;
    #pragma unroll
    for (int dd = 0; dd < 4; dd++) {
        int idx = t + dd * 256;
        partial += x[idx] * d_wmean[idx];
    }
    #pragma unroll
    for (int o = 16; o > 0; o >>= 1)
        partial += __shfl_xor_sync(0xffffffffu, partial, o);
    if ((t & 31) == 0) red[t >> 5] = partial;
    __syncthreads();
    if (t < 8) {
        float s = red[t];
        #pragma unroll
        for (int o = 4; o > 0; o >>= 1)
            s += __shfl_xor_sync(0xffu, s, o);
        if (t == 0) bc = s + d_bmean;
    }
    __syncthreads();
    float scalar = bc;

    #pragma unroll
    for (int dd = 0; dd < 4; dd++) {
        int idx = t + dd * 256;
        out[row * D + idx] = x[idx] + scalar;
    }
}

// ---------------------------------------------------------------------------
extern "C" void kernel_launch(void* const* d_in, const int* in_sizes, int n_in,
                              void* d_out, int out_size)
{
    const float* query = (const float*)d_in[0];
    const float* key_  = (const float*)d_in[1];
    const float* value = (const float*)d_in[2];
    const int*   mask  = (const int*)  d_in[3];
    const float* Wq    = (const float*)d_in[4];
    const float* bq    = (const float*)d_in[5];
    const float* Wk    = (const float*)d_in[6];
    const float* bk    = (const float*)d_in[7];
    const float* Wv    = (const float*)d_in[8];
    const float* bv    = (const float*)d_in[9];
    const float* Wo    = (const float*)d_in[10];
    const float* bo    = (const float*)d_in[11];
    float* out = (float*)d_out;

    float *Qp, *Kp, *Vp;
    cudaGetSymbolAddress((void**)&Qp, d_Q);
    cudaGetSymbolAddress((void**)&Kp, d_K);
    cudaGetSymbolAddress((void**)&Vp, d_V);

    dim3 gproj(D / 128, M / 128);                    // 8 x 32
    gemm_bias_kernel<<<gproj, 256>>>(query, Wq, bq, Qp);
    gemm_bias_kernel<<<gproj, 256>>>(key_,  Wk, bk, Kp);
    gemm_bias_kernel<<<gproj, 256>>>(value, Wv, bv, Vp);

    wmean_kernel<<<D / 32, 256>>>(Wo, bo);           // tiny

    dim3 gsc(S / 128, S / 128, B * H);               // 8 x 8 x 64
    scores_kernel<<<gsc, 256>>>(mask);

    softmax_kernel<<<B * H * S, 256>>>();            // 65536 rows

    dim3 gpv(1, S / 128, B * H);                     // 1 x 8 x 64
    pv_kernel<<<gpv, 256>>>();

    final_kernel<<<M, 256>>>(out);
}

// round 7
// speedup vs baseline: 2.5609x; 2.5244x over previous
#include <cuda_runtime.h>
#include <cuda_bf16.h>
#include <mma.h>
#include <cstdint>
#include <cstddef>

using namespace nvcuda;

// Problem constants
constexpr int B  = 4;
constexpr int S  = 1024;
constexpr int D  = 1024;
constexpr int H  = 16;
constexpr int DK = 64;
constexpr int M  = B * S;          // 4096

constexpr int LDT = 72;            // smem tile stride (64 + 8 pad), bf16 elems

// Scratch (device globals; allocation-free per harness rules)
__device__ __align__(16) unsigned short g_Qb[(size_t)M * D];          // bf16 [4096][1024]
__device__ __align__(16) unsigned short g_Kb[(size_t)M * D];          // bf16 [4096][1024]
__device__ __align__(16) unsigned short g_Vb[(size_t)M * D];          // bf16 [4096][1024]
__device__ __align__(16) unsigned short g_S [(size_t)B * H * S * S];  // bf16 [bh][q][k] (128MB)
__device__ float d_Xt[(size_t)M * D];
__device__ float d_wmean[D];
__device__ float d_bmean;

// ---------------------------------------------------------------------------
// Projection GEMM: dst[m,n] = bf16( A[m,:] . W[n,:] + bias[n] )
// M=4096, N=1024, K=1024.  CTA tile 128x128, BK=64, 256 threads (8 warps).
// Warp grid 2x4, warp tile 64x32 (4x2 WMMA 16x16x16 frags).
// ---------------------------------------------------------------------------
__global__ __launch_bounds__(256) void proj_kernel(
    const float* __restrict__ A, const float* __restrict__ W,
    const float* __restrict__ bias, unsigned short* __restrict__ dst)
{
    __shared__ __nv_bfloat16 sA[128 * LDT];
    __shared__ __nv_bfloat16 sB[128 * LDT];
    __shared__ float patch[8][256];

    const int t = threadIdx.x, wid = t >> 5, lane = t & 31;
    const int m0 = blockIdx.y * 128, n0 = blockIdx.x * 128;
    const int wm = wid >> 2, wn = wid & 3;     // 2 x 4 warps

    wmma::fragment<wmma::accumulator, 16, 16, 16, float> acc[4][2];
    #pragma unroll
    for (int i = 0; i < 4; i++)
        #pragma unroll
        for (int j = 0; j < 2; j++)
            wmma::fill_fragment(acc[i][j], 0.0f);

    for (int k0 = 0; k0 < 1024; k0 += 64) {
        #pragma unroll
        for (int i = t; i < 2048; i += 256) {       // A: 128 rows x 16 float4
            int r = i >> 4, c4 = i & 15;
            float4 v = *(const float4*)(A + (size_t)(m0 + r) * 1024 + k0 + c4 * 4);
            __nv_bfloat162 p0 = __float22bfloat162_rn(make_float2(v.x, v.y));
            __nv_bfloat162 p1 = __float22bfloat162_rn(make_float2(v.z, v.w));
            *(__nv_bfloat162*)&sA[r * LDT + c4 * 4]     = p0;
            *(__nv_bfloat162*)&sA[r * LDT + c4 * 4 + 2] = p1;
        }
        #pragma unroll
        for (int i = t; i < 2048; i += 256) {       // W: 128 n-rows x 16 float4
            int r = i >> 4, c4 = i & 15;
            float4 v = *(const float4*)(W + (size_t)(n0 + r) * 1024 + k0 + c4 * 4);
            __nv_bfloat162 p0 = __float22bfloat162_rn(make_float2(v.x, v.y));
            __nv_bfloat162 p1 = __float22bfloat162_rn(make_float2(v.z, v.w));
            *(__nv_bfloat162*)&sB[r * LDT + c4 * 4]     = p0;
            *(__nv_bfloat162*)&sB[r * LDT + c4 * 4 + 2] = p1;
        }
        __syncthreads();

        #pragma unroll
        for (int ks = 0; ks < 4; ks++) {
            wmma::fragment<wmma::matrix_a, 16, 16, 16, __nv_bfloat16, wmma::row_major> af[4];
            wmma::fragment<wmma::matrix_b, 16, 16, 16, __nv_bfloat16, wmma::col_major> bf[2];
            #pragma unroll
            for (int i = 0; i < 4; i++)
                wmma::load_matrix_sync(af[i], sA + (wm * 64 + i * 16) * LDT + ks * 16, LDT);
            #pragma unroll
            for (int j = 0; j < 2; j++)
                wmma::load_matrix_sync(bf[j], sB + (wn * 32 + j * 16) * LDT + ks * 16, LDT);
            #pragma unroll
            for (int i = 0; i < 4; i++)
                #pragma unroll
                for (int j = 0; j < 2; j++)
                    wmma::mma_sync(acc[i][j], af[i], bf[j], acc[i][j]);
        }
        __syncthreads();
    }

    #pragma unroll
    for (int i = 0; i < 4; i++) {
        #pragma unroll
        for (int j = 0; j < 2; j++) {
            wmma::store_matrix_sync(patch[wid], acc[i][j], 16, wmma::mem_row_major);
            __syncwarp();
            int mbase = m0 + wm * 64 + i * 16;
            int nbase = n0 + wn * 32 + j * 16;
            #pragma unroll
            for (int q = 0; q < 4; q++) {
                int idx = lane * 8 + q * 2;
                int rr = idx >> 4, cc = idx & 15;
                int n = nbase + cc;
                float lo = patch[wid][idx]     + bias[n];
                float hi = patch[wid][idx + 1] + bias[n + 1];
                __nv_bfloat162 p = __float22bfloat162_rn(make_float2(lo, hi));
                *(uint32_t*)&dst[(size_t)(mbase + rr) * 1024 + n] = *(uint32_t*)&p;
            }
            __syncwarp();
        }
    }
}

// ---------------------------------------------------------------------------
// Scores: S[bh,q,k] = (Q . K)/8, masked -> bf16.
// Grid (nt=8, mt=8, bh=64). CTA tile 128x128, K=64 single chunk.
// ---------------------------------------------------------------------------
__global__ __launch_bounds__(256) void scores_kernel(const int* __restrict__ mask)
{
    __shared__ __nv_bfloat16 sQ[128 * LDT];
    __shared__ __nv_bfloat16 sK[128 * LDT];
    __shared__ float patch[8][256];

    const int t = threadIdx.x, wid = t >> 5, lane = t & 31;
    const int nt = blockIdx.x, mt = blockIdx.y, bh = blockIdx.z;
    const int b = bh >> 4, h = bh & 15;
    const int wm = wid >> 2, wn = wid & 3;

    const unsigned short* Qsrc = g_Qb + ((size_t)(b * 1024 + mt * 128)) * 1024 + h * 64;
    const unsigned short* Ksrc = g_Kb + ((size_t)(b * 1024 + nt * 128)) * 1024 + h * 64;

    #pragma unroll
    for (int i = t; i < 1024; i += 256) {   // 128 rows x 8 uint4 (8 bf16 each)
        int r = i >> 3, q = i & 7;
        *(uint4*)&sQ[r * LDT + q * 8] = *(const uint4*)(Qsrc + (size_t)r * 1024 + q * 8);
    }
    #pragma unroll
    for (int i = t; i < 1024; i += 256) {
        int r = i >> 3, q = i & 7;
        *(uint4*)&sK[r * LDT + q * 8] = *(const uint4*)(Ksrc + (size_t)r * 1024 + q * 8);
    }
    __syncthreads();

    wmma::fragment<wmma::accumulator, 16, 16, 16, float> acc[4][2];
    #pragma unroll
    for (int i = 0; i < 4; i++)
        #pragma unroll
        for (int j = 0; j < 2; j++)
            wmma::fill_fragment(acc[i][j], 0.0f);

    #pragma unroll
    for (int ks = 0; ks < 4; ks++) {
        wmma::fragment<wmma::matrix_a, 16, 16, 16, __nv_bfloat16, wmma::row_major> af[4];
        wmma::fragment<wmma::matrix_b, 16, 16, 16, __nv_bfloat16, wmma::col_major> bf[2];
        #pragma unroll
        for (int i = 0; i < 4; i++)
            wmma::load_matrix_sync(af[i], sQ + (wm * 64 + i * 16) * LDT + ks * 16, LDT);
        #pragma unroll
        for (int j = 0; j < 2; j++)
            wmma::load_matrix_sync(bf[j], sK + (wn * 32 + j * 16) * LDT + ks * 16, LDT);
        #pragma unroll
        for (int i = 0; i < 4; i++)
            #pragma unroll
            for (int j = 0; j < 2; j++)
                wmma::mma_sync(acc[i][j], af[i], bf[j], acc[i][j]);
    }

    #pragma unroll
    for (int i = 0; i < 4; i++) {
        #pragma unroll
        for (int j = 0; j < 2; j++) {
            wmma::store_matrix_sync(patch[wid], acc[i][j], 16, wmma::mem_row_major);
            __syncwarp();
            int mbase = mt * 128 + wm * 64 + i * 16;
            int nbase = nt * 128 + wn * 32 + j * 16;
            #pragma unroll
            for (int q = 0; q < 4; q++) {
                int idx = lane * 8 + q * 2;
                int rr = idx >> 4, cc = idx & 15;
                int m = mbase + rr, n = nbase + cc;
                int2 mk = *(const int2*)&mask[((size_t)b * 1024 + m) * 1024 + n];
                float lo = patch[wid][idx]     * 0.125f;
                float hi = patch[wid][idx + 1] * 0.125f;
                if (mk.x == 0) lo = -1e9f;
                if (mk.y == 0) hi = -1e9f;
                __nv_bfloat162 p = __float22bfloat162_rn(make_float2(lo, hi));
                *(uint32_t*)&g_S[((size_t)bh * 1024 + m) * 1024 + n] = *(uint32_t*)&p;
            }
            __syncwarp();
        }
    }
}

// ---------------------------------------------------------------------------
// Row softmax over 1024 bf16 elements, in place. 256 threads, 4 elems each.
// ---------------------------------------------------------------------------
__global__ __launch_bounds__(256) void softmax_kernel()
{
    __shared__ float red[8];
    __shared__ float bc;

    const size_t row = blockIdx.x;
    unsigned short* p = g_S + row * 1024;
    const int t = threadIdx.x;

    uint2 u = *(const uint2*)(p + t * 4);
    float2 f0 = __bfloat1622float2(*(__nv_bfloat162*)&u.x);
    float2 f1 = __bfloat1622float2(*(__nv_bfloat162*)&u.y);

    float mx = fmaxf(fmaxf(f0.x, f0.y), fmaxf(f1.x, f1.y));
    #pragma unroll
    for (int o = 16; o > 0; o >>= 1) mx = fmaxf(mx, __shfl_xor_sync(0xffffffffu, mx, o));
    if ((t & 31) == 0) red[t >> 5] = mx;
    __syncthreads();
    if (t < 8) {
        float m2 = red[t];
        #pragma unroll
        for (int o = 4; o > 0; o >>= 1) m2 = fmaxf(m2, __shfl_xor_sync(0xffu, m2, o));
        if (t == 0) bc = m2;
    }
    __syncthreads();
    mx = bc;

    float e0 = __expf(f0.x - mx), e1 = __expf(f0.y - mx);
    float e2 = __expf(f1.x - mx), e3 = __expf(f1.y - mx);
    float sum = e0 + e1 + e2 + e3;
    #pragma unroll
    for (int o = 16; o > 0; o >>= 1) sum += __shfl_xor_sync(0xffffffffu, sum, o);
    if ((t & 31) == 0) red[t >> 5] = sum;
    __syncthreads();
    if (t < 8) {
        float s2 = red[t];
        #pragma unroll
        for (int o = 4; o > 0; o >>= 1) s2 += __shfl_xor_sync(0xffu, s2, o);
        if (t == 0) bc = s2;
    }
    __syncthreads();
    float inv = 1.0f / bc;

    __nv_bfloat162 o0 = __float22bfloat162_rn(make_float2(e0 * inv, e1 * inv));
    __nv_bfloat162 o1 = __float22bfloat162_rn(make_float2(e2 * inv, e3 * inv));
    uint2 w; w.x = *(uint32_t*)&o0; w.y = *(uint32_t*)&o1;
    *(uint2*)(p + t * 4) = w;
}

// ---------------------------------------------------------------------------
// PV: X[bh,q,dk] = P . V, threshold, write fp32 to d_Xt[b,s,h*64+dk].
// Grid (mt=8, bh=64). CTA tile 128(m) x 64(n), K=1024 in chunks of 64.
// Warp grid 4x2, warp tile 32x32 (2x2 frags).
// ---------------------------------------------------------------------------
__global__ __launch_bounds__(256) void pv_kernel()
{
    __shared__ __nv_bfloat16 sP[128 * LDT];
    __shared__ __nv_bfloat16 sV[64 * LDT];
    __shared__ float patch[8][256];

    const int t = threadIdx.x, wid = t >> 5, lane = t & 31;
    const int mt = blockIdx.x, bh = blockIdx.y;
    const int b = bh >> 4, h = bh & 15;
    const int wm = wid >> 1, wn = wid & 1;     // 4 x 2 warps

    wmma::fragment<wmma::accumulator, 16, 16, 16, float> acc[2][2];
    #pragma unroll
    for (int i = 0; i < 2; i++)
        #pragma unroll
        for (int j = 0; j < 2; j++)
            wmma::fill_fragment(acc[i][j], 0.0f);

    const unsigned short* Psrc = g_S + ((size_t)bh * 1024 + mt * 128) * 1024;
    const unsigned short* Vsrc = g_Vb + (size_t)b * 1024 * 1024 + h * 64;

    for (int k0 = 0; k0 < 1024; k0 += 64) {
        #pragma unroll
        for (int i = t; i < 1024; i += 256) {       // P tile 128 x 64
            int r = i >> 3, q = i & 7;
            *(uint4*)&sP[r * LDT + q * 8] =
                *(const uint4*)(Psrc + (size_t)r * 1024 + k0 + q * 8);
        }
        #pragma unroll
        for (int i = t; i < 512; i += 256) {        // V tile 64 x 64
            int r = i >> 3, q = i & 7;
            *(uint4*)&sV[r * LDT + q * 8] =
                *(const uint4*)(Vsrc + (size_t)(k0 + r) * 1024 + q * 8);
        }
        __syncthreads();

        #pragma unroll
        for (int ks = 0; ks < 4; ks++) {
            wmma::fragment<wmma::matrix_a, 16, 16, 16, __nv_bfloat16, wmma::row_major> af[2];
            wmma::fragment<wmma::matrix_b, 16, 16, 16, __nv_bfloat16, wmma::row_major> bf[2];
            #pragma unroll
            for (int i = 0; i < 2; i++)
                wmma::load_matrix_sync(af[i], sP + (wm * 32 + i * 16) * LDT + ks * 16, LDT);
            #pragma unroll
            for (int j = 0; j < 2; j++)
                wmma::load_matrix_sync(bf[j], sV + (ks * 16) * LDT + wn * 32 + j * 16, LDT);
            #pragma unroll
            for (int i = 0; i < 2; i++)
                #pragma unroll
                for (int j = 0; j < 2; j++)
                    wmma::mma_sync(acc[i][j], af[i], bf[j], acc[i][j]);
        }
        __syncthreads();
    }

    #pragma unroll
    for (int i = 0; i < 2; i++) {
        #pragma unroll
        for (int j = 0; j < 2; j++) {
            wmma::store_matrix_sync(patch[wid], acc[i][j], 16, wmma::mem_row_major);
            __syncwarp();
            int mbase = mt * 128 + wm * 32 + i * 16;
            int nbase = h * 64 + wn * 32 + j * 16;
            #pragma unroll
            for (int q = 0; q < 8; q++) {
                int idx = lane * 8 + q;
                int rr = idx >> 4, cc = idx & 15;
                float v = patch[wid][idx];
                v = (v > 0.2f) ? v : 0.0f;          // F.threshold(x, 0.2, 0.0)
                d_Xt[((size_t)b * 1024 + mbase + rr) * 1024 + nbase + cc] = v;
            }
            __syncwarp();
        }
    }
}

// ---------------------------------------------------------------------------
// Column means of Wo (and mean of bo)
// ---------------------------------------------------------------------------
__global__ __launch_bounds__(256) void wmean_kernel(const float* __restrict__ Wo,
                                                    const float* __restrict__ bo)
{
    __shared__ float sred[256];

    const int t    = threadIdx.x;
    const int col  = blockIdx.x * 32 + (t & 31);
    const int part = t >> 5;

    float s = 0.0f;
    const int nlo = part * 128, nhi = nlo + 128;
    for (int n = nlo; n < nhi; n++) s += Wo[(size_t)n * D + col];
    sred[t] = s;
    __syncthreads();

    if (part == 0) {
        float tot = 0.0f;
        #pragma unroll
        for (int p = 0; p < 8; p++) tot += sred[p * 32 + (t & 31)];
        d_wmean[col] = tot * (1.0f / D);
    }
    __syncthreads();

    if (blockIdx.x == 0) {
        float sb = 0.0f;
        #pragma unroll
        for (int i = t; i < D; i += 256) sb += bo[i];
        #pragma unroll
        for (int o = 16; o > 0; o >>= 1) sb += __shfl_xor_sync(0xffffffffu, sb, o);
        if ((t & 31) == 0) sred[t >> 5] = sb;
        __syncthreads();
        if (t == 0) {
            float x = 0.0f;
            #pragma unroll
            for (int p = 0; p < 8; p++) x += sred[p];
            d_bmean = x * (1.0f / D);
        }
    }
}

// ---------------------------------------------------------------------------
// Final: out[r,:] = Xt[r,:] + (Xt[r,:] . wmean + bmean)
// ---------------------------------------------------------------------------
__global__ __launch_bounds__(256) void final_kernel(float* __restrict__ out)
{
    __shared__ float red[8];
    __shared__ float bc;

    const size_t row = blockIdx.x;
    const float* x = d_Xt + row * D;
    const int t = threadIdx.x;

    float partial = 0.0f;
    #pragma unroll
    for (int dd = 0; dd < 4; dd++) {
        int idx = t + dd * 256;
        partial += x[idx] * d_wmean[idx];
    }
    #pragma unroll
    for (int o = 16; o > 0; o >>= 1) partial += __shfl_xor_sync(0xffffffffu, partial, o);
    if ((t & 31) == 0) red[t >> 5] = partial;
    __syncthreads();
    if (t < 8) {
        float s = red[t];
        #pragma unroll
        for (int o = 4; o > 0; o >>= 1) s += __shfl_xor_sync(0xffu, s, o);
        if (t == 0) bc = s + d_bmean;
    }
    __syncthreads();
    float scalar = bc;

    #pragma unroll
    for (int dd = 0; dd < 4; dd++) {
        int idx = t + dd * 256;
        out[row * D + idx] = x[idx] + scalar;
    }
}

// ---------------------------------------------------------------------------
extern "C" void kernel_launch(void* const* d_in, const int* in_sizes, int n_in,
                              void* d_out, int out_size)
{
    const float* query = (const float*)d_in[0];
    const float* key_  = (const float*)d_in[1];
    const float* value = (const float*)d_in[2];
    const int*   mask  = (const int*)  d_in[3];
    const float* Wq    = (const float*)d_in[4];
    const float* bq    = (const float*)d_in[5];
    const float* Wk    = (const float*)d_in[6];
    const float* bk    = (const float*)d_in[7];
    const float* Wv    = (const float*)d_in[8];
    const float* bv    = (const float*)d_in[9];
    const float* Wo    = (const float*)d_in[10];
    const float* bo    = (const float*)d_in[11];
    float* out = (float*)d_out;

    unsigned short *Qb, *Kb, *Vb;
    cudaGetSymbolAddress((void**)&Qb, g_Qb);
    cudaGetSymbolAddress((void**)&Kb, g_Kb);
    cudaGetSymbolAddress((void**)&Vb, g_Vb);

    dim3 gproj(8, 32);                                // n-tiles x m-tiles
    proj_kernel<<<gproj, 256>>>(query, Wq, bq, Qb);
    proj_kernel<<<gproj, 256>>>(key_,  Wk, bk, Kb);
    proj_kernel<<<gproj, 256>>>(value, Wv, bv, Vb);

    wmean_kernel<<<D / 32, 256>>>(Wo, bo);

    scores_kernel<<<dim3(8, 8, 64), 256>>>(mask);     // nt x mt x bh

    softmax_kernel<<<B * H * S, 256>>>();

    pv_kernel<<<dim3(8, 64), 256>>>();                // mt x bh

    final_kernel<<<M, 256>>>(out);
}

// round 8
// speedup vs baseline: 3.0861x; 1.2051x over previous
#include <cuda_runtime.h>
#include <cuda_bf16.h>
#include <mma.h>
#include <cstdint>
#include <cstddef>

using namespace nvcuda;

// Problem constants
constexpr int B  = 4;
constexpr int S  = 1024;
constexpr int D  = 1024;
constexpr int H  = 16;
constexpr int DK = 64;
constexpr int M  = B * S;          // 4096

constexpr int LDT = 72;            // smem stride for 64-wide tiles (pad 8)
constexpr int LDP = 136;           // smem stride for 128-wide P tile (pad 8)

// Scratch (device globals; allocation-free per harness rules)
__device__ __align__(16) unsigned short g_Qb[(size_t)M * D];   // bf16 [4096][1024]
__device__ __align__(16) unsigned short g_Kb[(size_t)M * D];   // bf16 [4096][1024]
__device__ __align__(16) unsigned short g_Vb[(size_t)M * D];   // bf16 [4096][1024]
__device__ float d_Xt[(size_t)M * D];
__device__ float d_wmean[D];
__device__ float d_bmean;

// ---------------------------------------------------------------------------
// Projection GEMM: dst[m,n] = bf16( A[m,:] . W[n,:] + bias[n] )
// M=4096, N=1024, K=1024.  CTA tile 128x128, BK=64, 256 threads (8 warps).
// ---------------------------------------------------------------------------
__global__ __launch_bounds__(256) void proj_kernel(
    const float* __restrict__ A, const float* __restrict__ W,
    const float* __restrict__ bias, unsigned short* __restrict__ dst)
{
    __shared__ __nv_bfloat16 sA[128 * LDT];
    __shared__ __nv_bfloat16 sB[128 * LDT];
    __shared__ float patch[8][256];

    const int t = threadIdx.x, wid = t >> 5, lane = t & 31;
    const int m0 = blockIdx.y * 128, n0 = blockIdx.x * 128;
    const int wm = wid >> 2, wn = wid & 3;     // 2 x 4 warps

    wmma::fragment<wmma::accumulator, 16, 16, 16, float> acc[4][2];
    #pragma unroll
    for (int i = 0; i < 4; i++)
        #pragma unroll
        for (int j = 0; j < 2; j++)
            wmma::fill_fragment(acc[i][j], 0.0f);

    for (int k0 = 0; k0 < 1024; k0 += 64) {
        #pragma unroll
        for (int i = t; i < 2048; i += 256) {
            int r = i >> 4, c4 = i & 15;
            float4 v = *(const float4*)(A + (size_t)(m0 + r) * 1024 + k0 + c4 * 4);
            __nv_bfloat162 p0 = __float22bfloat162_rn(make_float2(v.x, v.y));
            __nv_bfloat162 p1 = __float22bfloat162_rn(make_float2(v.z, v.w));
            *(__nv_bfloat162*)&sA[r * LDT + c4 * 4]     = p0;
            *(__nv_bfloat162*)&sA[r * LDT + c4 * 4 + 2] = p1;
        }
        #pragma unroll
        for (int i = t; i < 2048; i += 256) {
            int r = i >> 4, c4 = i & 15;
            float4 v = *(const float4*)(W + (size_t)(n0 + r) * 1024 + k0 + c4 * 4);
            __nv_bfloat162 p0 = __float22bfloat162_rn(make_float2(v.x, v.y));
            __nv_bfloat162 p1 = __float22bfloat162_rn(make_float2(v.z, v.w));
            *(__nv_bfloat162*)&sB[r * LDT + c4 * 4]     = p0;
            *(__nv_bfloat162*)&sB[r * LDT + c4 * 4 + 2] = p1;
        }
        __syncthreads();

        #pragma unroll
        for (int ks = 0; ks < 4; ks++) {
            wmma::fragment<wmma::matrix_a, 16, 16, 16, __nv_bfloat16, wmma::row_major> af[4];
            wmma::fragment<wmma::matrix_b, 16, 16, 16, __nv_bfloat16, wmma::col_major> bf[2];
            #pragma unroll
            for (int i = 0; i < 4; i++)
                wmma::load_matrix_sync(af[i], sA + (wm * 64 + i * 16) * LDT + ks * 16, LDT);
            #pragma unroll
            for (int j = 0; j < 2; j++)
                wmma::load_matrix_sync(bf[j], sB + (wn * 32 + j * 16) * LDT + ks * 16, LDT);
            #pragma unroll
            for (int i = 0; i < 4; i++)
                #pragma unroll
                for (int j = 0; j < 2; j++)
                    wmma::mma_sync(acc[i][j], af[i], bf[j], acc[i][j]);
        }
        __syncthreads();
    }

    #pragma unroll
    for (int i = 0; i < 4; i++) {
        #pragma unroll
        for (int j = 0; j < 2; j++) {
            wmma::store_matrix_sync(patch[wid], acc[i][j], 16, wmma::mem_row_major);
            __syncwarp();
            int mbase = m0 + wm * 64 + i * 16;
            int nbase = n0 + wn * 32 + j * 16;
            #pragma unroll
            for (int q = 0; q < 4; q++) {
                int idx = lane * 8 + q * 2;
                int rr = idx >> 4, cc = idx & 15;
                int n = nbase + cc;
                float lo = patch[wid][idx]     + bias[n];
                float hi = patch[wid][idx + 1] + bias[n + 1];
                __nv_bfloat162 p = __float22bfloat162_rn(make_float2(lo, hi));
                *(uint32_t*)&dst[(size_t)(mbase + rr) * 1024 + n] = *(uint32_t*)&p;
            }
            __syncwarp();
        }
    }
}

// ---------------------------------------------------------------------------
// Fused flash attention: per CTA = (q-tile mt, bh).
//   loop over 8 k-tiles:  S = Q.K^T /8 (WMMA)  -> mask -> exp (no max-sub,
//   clamped at -30 so fully-masked rows match reference's uniform softmax)
//   -> P bf16 in smem, row-sums accumulated in regs; O += P.V (WMMA).
//   Epilogue: O/rowsum, threshold 0.2, write fp32 to d_Xt.
// Dynamic smem layout (bytes):
//   sQ 0..18432 | sK ..36864 | sV ..55296 | sP ..90112 | patch ..98304 | srow ..98816
// ---------------------------------------------------------------------------
extern __shared__ char fa_smem[];

__global__ __launch_bounds__(256) void flash_kernel(const int* __restrict__ mask)
{
    __nv_bfloat16* sQ = (__nv_bfloat16*)(fa_smem);
    __nv_bfloat16* sK = (__nv_bfloat16*)(fa_smem + 18432);
    __nv_bfloat16* sV = (__nv_bfloat16*)(fa_smem + 36864);
    __nv_bfloat16* sP = (__nv_bfloat16*)(fa_smem + 55296);
    float* patch      = (float*)(fa_smem + 90112);   // [8][256]
    float* srow       = (float*)(fa_smem + 98304);   // [128]

    const int t = threadIdx.x, wid = t >> 5, lane = t & 31;
    const int mt = blockIdx.x, bh = blockIdx.y;
    const int b = bh >> 4, h = bh & 15;

    // warp grids
    const int wmS = wid >> 2, wnS = wid & 3;   // 2x4 for S (64x32 warp tile)
    const int wmO = wid >> 1, wnO = wid & 1;   // 4x2 for O (32x32 warp tile)

    float* mypatch = patch + wid * 256;

    if (t < 128) srow[t] = 0.0f;

    // Load Q tile (128 x 64) once
    const unsigned short* Qsrc = g_Qb + ((size_t)(b * 1024 + mt * 128)) * 1024 + h * 64;
    #pragma unroll
    for (int i = t; i < 1024; i += 256) {
        int r = i >> 3, q = i & 7;
        *(uint4*)&sQ[r * LDT + q * 8] = *(const uint4*)(Qsrc + (size_t)r * 1024 + q * 8);
    }

    wmma::fragment<wmma::accumulator, 16, 16, 16, float> oacc[2][2];
    #pragma unroll
    for (int i = 0; i < 2; i++)
        #pragma unroll
        for (int j = 0; j < 2; j++)
            wmma::fill_fragment(oacc[i][j], 0.0f);

    float rs[4] = {0.0f, 0.0f, 0.0f, 0.0f};   // row-sum partials (per i-frag)

    const int qrow0 = mt * 128;                 // q offset within batch

    for (int kt = 0; kt < 8; kt++) {
        // Load K, V tiles (128 x 64 each)
        const unsigned short* Ksrc = g_Kb + ((size_t)(b * 1024 + kt * 128)) * 1024 + h * 64;
        const unsigned short* Vsrc = g_Vb + ((size_t)(b * 1024 + kt * 128)) * 1024 + h * 64;
        #pragma unroll
        for (int i = t; i < 1024; i += 256) {
            int r = i >> 3, q = i & 7;
            *(uint4*)&sK[r * LDT + q * 8] = *(const uint4*)(Ksrc + (size_t)r * 1024 + q * 8);
        }
        #pragma unroll
        for (int i = t; i < 1024; i += 256) {
            int r = i >> 3, q = i & 7;
            *(uint4*)&sV[r * LDT + q * 8] = *(const uint4*)(Vsrc + (size_t)r * 1024 + q * 8);
        }
        __syncthreads();

        // ---- S = Q.K^T (128x128), warp tile 64x32 ----
        wmma::fragment<wmma::accumulator, 16, 16, 16, float> sacc[4][2];
        #pragma unroll
        for (int i = 0; i < 4; i++)
            #pragma unroll
            for (int j = 0; j < 2; j++)
                wmma::fill_fragment(sacc[i][j], 0.0f);

        #pragma unroll
        for (int ks = 0; ks < 4; ks++) {
            wmma::fragment<wmma::matrix_a, 16, 16, 16, __nv_bfloat16, wmma::row_major> af[4];
            wmma::fragment<wmma::matrix_b, 16, 16, 16, __nv_bfloat16, wmma::col_major> bf[2];
            #pragma unroll
            for (int i = 0; i < 4; i++)
                wmma::load_matrix_sync(af[i], sQ + (wmS * 64 + i * 16) * LDT + ks * 16, LDT);
            #pragma unroll
            for (int j = 0; j < 2; j++)
                wmma::load_matrix_sync(bf[j], sK + (wnS * 32 + j * 16) * LDT + ks * 16, LDT);
            #pragma unroll
            for (int i = 0; i < 4; i++)
                #pragma unroll
                for (int j = 0; j < 2; j++)
                    wmma::mma_sync(sacc[i][j], af[i], bf[j], sacc[i][j]);
        }

        // ---- scale, mask, exp -> sP (bf16); accumulate row sums in regs ----
        #pragma unroll
        for (int i = 0; i < 4; i++) {
            #pragma unroll
            for (int j = 0; j < 2; j++) {
                wmma::store_matrix_sync(mypatch, sacc[i][j], 16, wmma::mem_row_major);
                __syncwarp();
                int mrel = wmS * 64 + i * 16 + (lane >> 1);         // row in tile
                int nrel = wnS * 32 + j * 16 + (lane & 1) * 8;      // col in tile
                int mglob = qrow0 + mrel;
                int nglob = kt * 128 + nrel;
                const int* mrow = mask + ((size_t)b * 1024 + mglob) * 1024 + nglob;
                int base = (lane >> 1) * 16 + (lane & 1) * 8;
                float acc8 = 0.0f;
                #pragma unroll
                for (int q = 0; q < 8; q += 2) {
                    int2 mk = *(const int2*)(mrow + q);
                    float lo = mypatch[base + q]     * 0.125f;
                    float hi = mypatch[base + q + 1] * 0.125f;
                    if (mk.x == 0) lo = -1e9f;
                    if (mk.y == 0) hi = -1e9f;
                    float e0 = __expf(fmaxf(lo, -30.0f));
                    float e1 = __expf(fmaxf(hi, -30.0f));
                    acc8 += e0 + e1;
                    __nv_bfloat162 p = __float22bfloat162_rn(make_float2(e0, e1));
                    *(uint32_t*)&sP[mrel * LDP + nrel + q] = *(uint32_t*)&p;
                }
                rs[i] += acc8;
                __syncwarp();
            }
        }
        __syncthreads();

        // ---- O += P.V  (128x64), warp tile 32x32 ----
        #pragma unroll
        for (int ks = 0; ks < 8; ks++) {
            wmma::fragment<wmma::matrix_a, 16, 16, 16, __nv_bfloat16, wmma::row_major> af[2];
            wmma::fragment<wmma::matrix_b, 16, 16, 16, __nv_bfloat16, wmma::row_major> bf[2];
            #pragma unroll
            for (int i = 0; i < 2; i++)
                wmma::load_matrix_sync(af[i], sP + (wmO * 32 + i * 16) * LDP + ks * 16, LDP);
            #pragma unroll
            for (int j = 0; j < 2; j++)
                wmma::load_matrix_sync(bf[j], sV + (ks * 16) * LDT + wnO * 32 + j * 16, LDT);
            #pragma unroll
            for (int i = 0; i < 2; i++)
                #pragma unroll
                for (int j = 0; j < 2; j++)
                    wmma::mma_sync(oacc[i][j], af[i], bf[j], oacc[i][j]);
        }
        __syncthreads();
    }

    // ---- finalize row sums ----
    #pragma unroll
    for (int i = 0; i < 4; i++) {
        int mrel = wmS * 64 + i * 16 + (lane >> 1);
        atomicAdd(&srow[mrel], rs[i]);
    }
    __syncthreads();

    // ---- epilogue: O / rowsum, threshold, write fp32 ----
    #pragma unroll
    for (int i = 0; i < 2; i++) {
        #pragma unroll
        for (int j = 0; j < 2; j++) {
            wmma::store_matrix_sync(mypatch, oacc[i][j], 16, wmma::mem_row_major);
            __syncwarp();
            int mrel = wmO * 32 + i * 16 + (lane >> 1);
            int dk0  = wnO * 32 + j * 16 + (lane & 1) * 8;
            float inv = 1.0f / srow[mrel];
            int base = (lane >> 1) * 16 + (lane & 1) * 8;
            size_t orow = ((size_t)b * 1024 + qrow0 + mrel) * 1024 + h * 64 + dk0;
            #pragma unroll
            for (int q = 0; q < 8; q++) {
                float v = mypatch[base + q] * inv;
                v = (v > 0.2f) ? v : 0.0f;        // F.threshold(x, 0.2, 0.0)
                d_Xt[orow + q] = v;
            }
            __syncwarp();
        }
    }
}

// ---------------------------------------------------------------------------
// Column means of Wo (and mean of bo)
// ---------------------------------------------------------------------------
__global__ __launch_bounds__(256) void wmean_kernel(const float* __restrict__ Wo,
                                                    const float* __restrict__ bo)
{
    __shared__ float sred[256];

    const int t    = threadIdx.x;
    const int col  = blockIdx.x * 32 + (t & 31);
    const int part = t >> 5;

    float s = 0.0f;
    const int nlo = part * 128, nhi = nlo + 128;
    for (int n = nlo; n < nhi; n++) s += Wo[(size_t)n * D + col];
    sred[t] = s;
    __syncthreads();

    if (part == 0) {
        float tot = 0.0f;
        #pragma unroll
        for (int p = 0; p < 8; p++) tot += sred[p * 32 + (t & 31)];
        d_wmean[col] = tot * (1.0f / D);
    }
    __syncthreads();

    if (blockIdx.x == 0) {
        float sb = 0.0f;
        #pragma unroll
        for (int i = t; i < D; i += 256) sb += bo[i];
        #pragma unroll
        for (int o = 16; o > 0; o >>= 1) sb += __shfl_xor_sync(0xffffffffu, sb, o);
        if ((t & 31) == 0) sred[t >> 5] = sb;
        __syncthreads();
        if (t == 0) {
            float x = 0.0f;
            #pragma unroll
            for (int p = 0; p < 8; p++) x += sred[p];
            d_bmean = x * (1.0f / D);
        }
    }
}

// ---------------------------------------------------------------------------
// Final: out[r,:] = Xt[r,:] + (Xt[r,:] . wmean + bmean)
// ---------------------------------------------------------------------------
__global__ __launch_bounds__(256) void final_kernel(float* __restrict__ out)
{
    __shared__ float red[8];
    __shared__ float bc;

    const size_t row = blockIdx.x;
    const float* x = d_Xt + row * D;
    const int t = threadIdx.x;

    float partial = 0.0f;
    #pragma unroll
    for (int dd = 0; dd < 4; dd++) {
        int idx = t + dd * 256;
        partial += x[idx] * d_wmean[idx];
    }
    #pragma unroll
    for (int o = 16; o > 0; o >>= 1) partial += __shfl_xor_sync(0xffffffffu, partial, o);
    if ((t & 31) == 0) red[t >> 5] = partial;
    __syncthreads();
    if (t < 8) {
        float s = red[t];
        #pragma unroll
        for (int o = 4; o > 0; o >>= 1) s += __shfl_xor_sync(0xffu, s, o);
        if (t == 0) bc = s + d_bmean;
    }
    __syncthreads();
    float scalar = bc;

    #pragma unroll
    for (int dd = 0; dd < 4; dd++) {
        int idx = t + dd * 256;
        out[row * D + idx] = x[idx] + scalar;
    }
}

// ---------------------------------------------------------------------------
extern "C" void kernel_launch(void* const* d_in, const int* in_sizes, int n_in,
                              void* d_out, int out_size)
{
    const float* query = (const float*)d_in[0];
    const float* key_  = (const float*)d_in[1];
    const float* value = (const float*)d_in[2];
    const int*   mask  = (const int*)  d_in[3];
    const float* Wq    = (const float*)d_in[4];
    const float* bq    = (const float*)d_in[5];
    const float* Wk    = (const float*)d_in[6];
    const float* bk    = (const float*)d_in[7];
    const float* Wv    = (const float*)d_in[8];
    const float* bv    = (const float*)d_in[9];
    const float* Wo    = (const float*)d_in[10];
    const float* bo    = (const float*)d_in[11];
    float* out = (float*)d_out;

    unsigned short *Qb, *Kb, *Vb;
    cudaGetSymbolAddress((void**)&Qb, g_Qb);
    cudaGetSymbolAddress((void**)&Kb, g_Kb);
    cudaGetSymbolAddress((void**)&Vb, g_Vb);

    constexpr int FA_SMEM = 98816;
    cudaFuncSetAttribute(flash_kernel, cudaFuncAttributeMaxDynamicSharedMemorySize, FA_SMEM);

    dim3 gproj(8, 32);                                // n-tiles x m-tiles
    proj_kernel<<<gproj, 256>>>(query, Wq, bq, Qb);
    proj_kernel<<<gproj, 256>>>(key_,  Wk, bk, Kb);
    proj_kernel<<<gproj, 256>>>(value, Wv, bv, Vb);

    wmean_kernel<<<D / 32, 256>>>(Wo, bo);

    flash_kernel<<<dim3(8, 64), 256, FA_SMEM>>>(mask); // mt x bh

    final_kernel<<<M, 256>>>(out);
}

// round 9
// speedup vs baseline: 3.8055x; 1.2331x over previous
#include <cuda_runtime.h>
#include <cuda_bf16.h>
#include <mma.h>
#include <cstdint>
#include <cstddef>

using namespace nvcuda;

// Problem constants
constexpr int B  = 4;
constexpr int S  = 1024;
constexpr int D  = 1024;
constexpr int H  = 16;
constexpr int DK = 64;
constexpr int M  = B * S;          // 4096

constexpr int LDT = 72;            // smem stride for 64-wide tiles (pad 8) -> 144B rows (16B-aligned)
constexpr int LDP = 136;           // smem stride for 128-wide P tile

// Scratch (device globals; allocation-free per harness rules)
__device__ __align__(16) unsigned short g_qin[(size_t)M * D];   // bf16 inputs
__device__ __align__(16) unsigned short g_kin[(size_t)M * D];
__device__ __align__(16) unsigned short g_vin[(size_t)M * D];
__device__ __align__(16) unsigned short g_wq [(size_t)D * D];   // bf16 weights
__device__ __align__(16) unsigned short g_wk [(size_t)D * D];
__device__ __align__(16) unsigned short g_wv [(size_t)D * D];
__device__ __align__(16) unsigned short g_Qb[(size_t)M * D];    // bf16 projected
__device__ __align__(16) unsigned short g_Kb[(size_t)M * D];
__device__ __align__(16) unsigned short g_Vb[(size_t)M * D];
__device__ float d_Xt[(size_t)M * D];
__device__ float d_wmean[D];
__device__ float d_bmean;

// ---------------------------------------------------------------------------
__device__ __forceinline__ uint32_t smem_u32(const void* p) {
    uint32_t a;
    asm("{ .reg .u64 t; cvta.to.shared.u64 t, %1; cvt.u32.u64 %0, t; }" : "=r"(a) : "l"(p));
    return a;
}
#define CP_ASYNC16(dst, src) \
    asm volatile("cp.async.cg.shared.global [%0], [%1], 16;" :: "r"(dst), "l"(src) : "memory")
#define CP_COMMIT()  asm volatile("cp.async.commit_group;" ::: "memory")
#define CP_WAIT(n)   asm volatile("cp.async.wait_group %0;" :: "n"(n) : "memory")

// ---------------------------------------------------------------------------
// fp32 -> bf16 convert pass: 3 inputs (4M elems each) + 3 weights (1M each)
// grid (nblk, 6), vectorized float4 -> bf16x4.
// ---------------------------------------------------------------------------
__global__ __launch_bounds__(256) void conv_kernel(
    const float* __restrict__ q,  const float* __restrict__ k,  const float* __restrict__ v,
    const float* __restrict__ wq, const float* __restrict__ wk, const float* __restrict__ wv)
{
    const int z = blockIdx.y;
    const float* src; unsigned short* dst; size_t n4;
    switch (z) {
        case 0: src = q;  dst = g_qin; n4 = (size_t)M * D / 4; break;
        case 1: src = k;  dst = g_kin; n4 = (size_t)M * D / 4; break;
        case 2: src = v;  dst = g_vin; n4 = (size_t)M * D / 4; break;
        case 3: src = wq; dst = g_wq;  n4 = (size_t)D * D / 4; break;
        case 4: src = wk; dst = g_wk;  n4 = (size_t)D * D / 4; break;
        default: src = wv; dst = g_wv; n4 = (size_t)D * D / 4; break;
    }
    for (size_t i = (size_t)blockIdx.x * 256 + threadIdx.x; i < n4;
         i += (size_t)gridDim.x * 256) {
        float4 f = ((const float4*)src)[i];
        __nv_bfloat162 p0 = __float22bfloat162_rn(make_float2(f.x, f.y));
        __nv_bfloat162 p1 = __float22bfloat162_rn(make_float2(f.z, f.w));
        uint2 o; o.x = *(uint32_t*)&p0; o.y = *(uint32_t*)&p1;
        ((uint2*)dst)[i] = o;
    }
}

// ---------------------------------------------------------------------------
// Fused QKV projection: grid (8 n-tiles, 32 m-tiles, 3 proj).
// dst[m,n] = bf16( A[m,:] . W[n,:] + bias[n] ),  all operands bf16 in gmem.
// CTA tile 128x128, BK=64, 256 threads (8 warps, 2x4, warp tile 64x32).
// cp.async double-buffered smem pipeline.
// ---------------------------------------------------------------------------
__global__ __launch_bounds__(256) void proj_kernel(
    const float* __restrict__ bq, const float* __restrict__ bk,
    const float* __restrict__ bv)
{
    __shared__ __nv_bfloat16 sA[2][128 * LDT];
    __shared__ __nv_bfloat16 sB[2][128 * LDT];
    __shared__ float patch[8][256];

    const int t = threadIdx.x, wid = t >> 5, lane = t & 31;
    const int m0 = blockIdx.y * 128, n0 = blockIdx.x * 128;
    const int z  = blockIdx.z;
    const int wm = wid >> 2, wn = wid & 3;     // 2 x 4 warps

    const unsigned short* Ain; const unsigned short* Wb;
    const float* bias; unsigned short* dst;
    switch (z) {
        case 0: Ain = g_qin; Wb = g_wq; bias = bq; dst = g_Qb; break;
        case 1: Ain = g_kin; Wb = g_wk; bias = bk; dst = g_Kb; break;
        default: Ain = g_vin; Wb = g_wv; bias = bv; dst = g_Vb; break;
    }
    const unsigned short* Asrc = Ain + (size_t)m0 * 1024;
    const unsigned short* Wsrc = Wb  + (size_t)n0 * 1024;

    const uint32_t uA = smem_u32(sA), uB = smem_u32(sB);
    constexpr uint32_t TILEB = 128 * LDT * 2;   // bytes per buffer

    // issue cp.async for one k-chunk into buffer `buf`
    auto stage = [&](int k0, int buf) {
        #pragma unroll
        for (int i = t; i < 1024; i += 256) {          // A: 128 rows x 8 chunks
            int r = i >> 3, q = i & 7;
            CP_ASYNC16(uA + buf * TILEB + (uint32_t)(r * LDT + q * 8) * 2,
                       Asrc + (size_t)r * 1024 + k0 + q * 8);
        }
        #pragma unroll
        for (int i = t; i < 1024; i += 256) {          // W: 128 n-rows x 8 chunks
            int r = i >> 3, q = i & 7;
            CP_ASYNC16(uB + buf * TILEB + (uint32_t)(r * LDT + q * 8) * 2,
                       Wsrc + (size_t)r * 1024 + k0 + q * 8);
        }
        CP_COMMIT();
    };

    wmma::fragment<wmma::accumulator, 16, 16, 16, float> acc[4][2];
    #pragma unroll
    for (int i = 0; i < 4; i++)
        #pragma unroll
        for (int j = 0; j < 2; j++)
            wmma::fill_fragment(acc[i][j], 0.0f);

    stage(0, 0);

    for (int k0 = 0; k0 < 1024; k0 += 64) {
        const int buf = (k0 >> 6) & 1;
        if (k0 + 64 < 1024) {
            stage(k0 + 64, buf ^ 1);
            CP_WAIT(1);                  // current buffer's group complete
        } else {
            CP_WAIT(0);
        }
        __syncthreads();

        #pragma unroll
        for (int ks = 0; ks < 4; ks++) {
            wmma::fragment<wmma::matrix_a, 16, 16, 16, __nv_bfloat16, wmma::row_major> af[4];
            wmma::fragment<wmma::matrix_b, 16, 16, 16, __nv_bfloat16, wmma::col_major> bf[2];
            #pragma unroll
            for (int i = 0; i < 4; i++)
                wmma::load_matrix_sync(af[i], sA[buf] + (wm * 64 + i * 16) * LDT + ks * 16, LDT);
            #pragma unroll
            for (int j = 0; j < 2; j++)
                wmma::load_matrix_sync(bf[j], sB[buf] + (wn * 32 + j * 16) * LDT + ks * 16, LDT);
            #pragma unroll
            for (int i = 0; i < 4; i++)
                #pragma unroll
                for (int j = 0; j < 2; j++)
                    wmma::mma_sync(acc[i][j], af[i], bf[j], acc[i][j]);
        }
        __syncthreads();
    }

    #pragma unroll
    for (int i = 0; i < 4; i++) {
        #pragma unroll
        for (int j = 0; j < 2; j++) {
            wmma::store_matrix_sync(patch[wid], acc[i][j], 16, wmma::mem_row_major);
            __syncwarp();
            int mbase = m0 + wm * 64 + i * 16;
            int nbase = n0 + wn * 32 + j * 16;
            #pragma unroll
            for (int q = 0; q < 4; q++) {
                int idx = lane * 8 + q * 2;
                int rr = idx >> 4, cc = idx & 15;
                int n = nbase + cc;
                float lo = patch[wid][idx]     + bias[n];
                float hi = patch[wid][idx + 1] + bias[n + 1];
                __nv_bfloat162 p = __float22bfloat162_rn(make_float2(lo, hi));
                *(uint32_t*)&dst[(size_t)(mbase + rr) * 1024 + n] = *(uint32_t*)&p;
            }
            __syncwarp();
        }
    }
}

// ---------------------------------------------------------------------------
// Fused flash attention (unchanged from R8): per CTA = (q-tile mt, bh).
// ---------------------------------------------------------------------------
extern __shared__ char fa_smem[];

__global__ __launch_bounds__(256) void flash_kernel(const int* __restrict__ mask)
{
    __nv_bfloat16* sQ = (__nv_bfloat16*)(fa_smem);
    __nv_bfloat16* sK = (__nv_bfloat16*)(fa_smem + 18432);
    __nv_bfloat16* sV = (__nv_bfloat16*)(fa_smem + 36864);
    __nv_bfloat16* sP = (__nv_bfloat16*)(fa_smem + 55296);
    float* patch      = (float*)(fa_smem + 90112);   // [8][256]
    float* srow       = (float*)(fa_smem + 98304);   // [128]

    const int t = threadIdx.x, wid = t >> 5, lane = t & 31;
    const int mt = blockIdx.x, bh = blockIdx.y;
    const int b = bh >> 4, h = bh & 15;

    const int wmS = wid >> 2, wnS = wid & 3;   // 2x4 for S (64x32 warp tile)
    const int wmO = wid >> 1, wnO = wid & 1;   // 4x2 for O (32x32 warp tile)

    float* mypatch = patch + wid * 256;

    if (t < 128) srow[t] = 0.0f;

    const unsigned short* Qsrc = g_Qb + ((size_t)(b * 1024 + mt * 128)) * 1024 + h * 64;
    #pragma unroll
    for (int i = t; i < 1024; i += 256) {
        int r = i >> 3, q = i & 7;
        *(uint4*)&sQ[r * LDT + q * 8] = *(const uint4*)(Qsrc + (size_t)r * 1024 + q * 8);
    }

    wmma::fragment<wmma::accumulator, 16, 16, 16, float> oacc[2][2];
    #pragma unroll
    for (int i = 0; i < 2; i++)
        #pragma unroll
        for (int j = 0; j < 2; j++)
            wmma::fill_fragment(oacc[i][j], 0.0f);

    float rs[4] = {0.0f, 0.0f, 0.0f, 0.0f};
    const int qrow0 = mt * 128;

    for (int kt = 0; kt < 8; kt++) {
        const unsigned short* Ksrc = g_Kb + ((size_t)(b * 1024 + kt * 128)) * 1024 + h * 64;
        const unsigned short* Vsrc = g_Vb + ((size_t)(b * 1024 + kt * 128)) * 1024 + h * 64;
        #pragma unroll
        for (int i = t; i < 1024; i += 256) {
            int r = i >> 3, q = i & 7;
            *(uint4*)&sK[r * LDT + q * 8] = *(const uint4*)(Ksrc + (size_t)r * 1024 + q * 8);
        }
        #pragma unroll
        for (int i = t; i < 1024; i += 256) {
            int r = i >> 3, q = i & 7;
            *(uint4*)&sV[r * LDT + q * 8] = *(const uint4*)(Vsrc + (size_t)r * 1024 + q * 8);
        }
        __syncthreads();

        wmma::fragment<wmma::accumulator, 16, 16, 16, float> sacc[4][2];
        #pragma unroll
        for (int i = 0; i < 4; i++)
            #pragma unroll
            for (int j = 0; j < 2; j++)
                wmma::fill_fragment(sacc[i][j], 0.0f);

        #pragma unroll
        for (int ks = 0; ks < 4; ks++) {
            wmma::fragment<wmma::matrix_a, 16, 16, 16, __nv_bfloat16, wmma::row_major> af[4];
            wmma::fragment<wmma::matrix_b, 16, 16, 16, __nv_bfloat16, wmma::col_major> bf[2];
            #pragma unroll
            for (int i = 0; i < 4; i++)
                wmma::load_matrix_sync(af[i], sQ + (wmS * 64 + i * 16) * LDT + ks * 16, LDT);
            #pragma unroll
            for (int j = 0; j < 2; j++)
                wmma::load_matrix_sync(bf[j], sK + (wnS * 32 + j * 16) * LDT + ks * 16, LDT);
            #pragma unroll
            for (int i = 0; i < 4; i++)
                #pragma unroll
                for (int j = 0; j < 2; j++)
                    wmma::mma_sync(sacc[i][j], af[i], bf[j], sacc[i][j]);
        }

        #pragma unroll
        for (int i = 0; i < 4; i++) {
            #pragma unroll
            for (int j = 0; j < 2; j++) {
                wmma::store_matrix_sync(mypatch, sacc[i][j], 16, wmma::mem_row_major);
                __syncwarp();
                int mrel = wmS * 64 + i * 16 + (lane >> 1);
                int nrel = wnS * 32 + j * 16 + (lane & 1) * 8;
                int mglob = qrow0 + mrel;
                int nglob = kt * 128 + nrel;
                const int* mrow = mask + ((size_t)b * 1024 + mglob) * 1024 + nglob;
                int base = (lane >> 1) * 16 + (lane & 1) * 8;
                float acc8 = 0.0f;
                #pragma unroll
                for (int q = 0; q < 8; q += 2) {
                    int2 mk = *(const int2*)(mrow + q);
                    float lo = mypatch[base + q]     * 0.125f;
                    float hi = mypatch[base + q + 1] * 0.125f;
                    if (mk.x == 0) lo = -1e9f;
                    if (mk.y == 0) hi = -1e9f;
                    float e0 = __expf(fmaxf(lo, -30.0f));
                    float e1 = __expf(fmaxf(hi, -30.0f));
                    acc8 += e0 + e1;
                    __nv_bfloat162 p = __float22bfloat162_rn(make_float2(e0, e1));
                    *(uint32_t*)&sP[mrel * LDP + nrel + q] = *(uint32_t*)&p;
                }
                rs[i] += acc8;
                __syncwarp();
            }
        }
        __syncthreads();

        #pragma unroll
        for (int ks = 0; ks < 8; ks++) {
            wmma::fragment<wmma::matrix_a, 16, 16, 16, __nv_bfloat16, wmma::row_major> af[2];
            wmma::fragment<wmma::matrix_b, 16, 16, 16, __nv_bfloat16, wmma::row_major> bf[2];
            #pragma unroll
            for (int i = 0; i < 2; i++)
                wmma::load_matrix_sync(af[i], sP + (wmO * 32 + i * 16) * LDP + ks * 16, LDP);
            #pragma unroll
            for (int j = 0; j < 2; j++)
                wmma::load_matrix_sync(bf[j], sV + (ks * 16) * LDT + wnO * 32 + j * 16, LDT);
            #pragma unroll
            for (int i = 0; i < 2; i++)
                #pragma unroll
                for (int j = 0; j < 2; j++)
                    wmma::mma_sync(oacc[i][j], af[i], bf[j], oacc[i][j]);
        }
        __syncthreads();
    }

    #pragma unroll
    for (int i = 0; i < 4; i++) {
        int mrel = wmS * 64 + i * 16 + (lane >> 1);
        atomicAdd(&srow[mrel], rs[i]);
    }
    __syncthreads();

    #pragma unroll
    for (int i = 0; i < 2; i++) {
        #pragma unroll
        for (int j = 0; j < 2; j++) {
            wmma::store_matrix_sync(mypatch, oacc[i][j], 16, wmma::mem_row_major);
            __syncwarp();
            int mrel = wmO * 32 + i * 16 + (lane >> 1);
            int dk0  = wnO * 32 + j * 16 + (lane & 1) * 8;
            float inv = 1.0f / srow[mrel];
            int base = (lane >> 1) * 16 + (lane & 1) * 8;
            size_t orow = ((size_t)b * 1024 + qrow0 + mrel) * 1024 + h * 64 + dk0;
            #pragma unroll
            for (int q = 0; q < 8; q++) {
                float v = mypatch[base + q] * inv;
                v = (v > 0.2f) ? v : 0.0f;        // F.threshold(x, 0.2, 0.0)
                d_Xt[orow + q] = v;
            }
            __syncwarp();
        }
    }
}

// ---------------------------------------------------------------------------
// Column means of Wo (and mean of bo)
// ---------------------------------------------------------------------------
__global__ __launch_bounds__(256) void wmean_kernel(const float* __restrict__ Wo,
                                                    const float* __restrict__ bo)
{
    __shared__ float sred[256];

    const int t    = threadIdx.x;
    const int col  = blockIdx.x * 32 + (t & 31);
    const int part = t >> 5;

    float s = 0.0f;
    const int nlo = part * 128, nhi = nlo + 128;
    for (int n = nlo; n < nhi; n++) s += Wo[(size_t)n * D + col];
    sred[t] = s;
    __syncthreads();

    if (part == 0) {
        float tot = 0.0f;
        #pragma unroll
        for (int p = 0; p < 8; p++) tot += sred[p * 32 + (t & 31)];
        d_wmean[col] = tot * (1.0f / D);
    }
    __syncthreads();

    if (blockIdx.x == 0) {
        float sb = 0.0f;
        #pragma unroll
        for (int i = t; i < D; i += 256) sb += bo[i];
        #pragma unroll
        for (int o = 16; o > 0; o >>= 1) sb += __shfl_xor_sync(0xffffffffu, sb, o);
        if ((t & 31) == 0) sred[t >> 5] = sb;
        __syncthreads();
        if (t == 0) {
            float x = 0.0f;
            #pragma unroll
            for (int p = 0; p < 8; p++) x += sred[p];
            d_bmean = x * (1.0f / D);
        }
    }
}

// ---------------------------------------------------------------------------
// Final: out[r,:] = Xt[r,:] + (Xt[r,:] . wmean + bmean)
// ---------------------------------------------------------------------------
__global__ __launch_bounds__(256) void final_kernel(float* __restrict__ out)
{
    __shared__ float red[8];
    __shared__ float bc;

    const size_t row = blockIdx.x;
    const float* x = d_Xt + row * D;
    const int t = threadIdx.x;

    float partial = 0.0f;
    #pragma unroll
    for (int dd = 0; dd < 4; dd++) {
        int idx = t + dd * 256;
        partial += x[idx] * d_wmean[idx];
    }
    #pragma unroll
    for (int o = 16; o > 0; o >>= 1) partial += __shfl_xor_sync(0xffffffffu, partial, o);
    if ((t & 31) == 0) red[t >> 5] = partial;
    __syncthreads();
    if (t < 8) {
        float s = red[t];
        #pragma unroll
        for (int o = 4; o > 0; o >>= 1) s += __shfl_xor_sync(0xffu, s, o);
        if (t == 0) bc = s + d_bmean;
    }
    __syncthreads();
    float scalar = bc;

    #pragma unroll
    for (int dd = 0; dd < 4; dd++) {
        int idx = t + dd * 256;
        out[row * D + idx] = x[idx] + scalar;
    }
}

// ---------------------------------------------------------------------------
extern "C" void kernel_launch(void* const* d_in, const int* in_sizes, int n_in,
                              void* d_out, int out_size)
{
    const float* query = (const float*)d_in[0];
    const float* key_  = (const float*)d_in[1];
    const float* value = (const float*)d_in[2];
    const int*   mask  = (const int*)  d_in[3];
    const float* Wq    = (const float*)d_in[4];
    const float* bq    = (const float*)d_in[5];
    const float* Wk    = (const float*)d_in[6];
    const float* bk    = (const float*)d_in[7];
    const float* Wv    = (const float*)d_in[8];
    const float* bv    = (const float*)d_in[9];
    const float* Wo    = (const float*)d_in[10];
    const float* bo    = (const float*)d_in[11];
    float* out = (float*)d_out;

    constexpr int FA_SMEM = 98816;
    cudaFuncSetAttribute(flash_kernel, cudaFuncAttributeMaxDynamicSharedMemorySize, FA_SMEM);

    conv_kernel<<<dim3(256, 6), 256>>>(query, key_, value, Wq, Wk, Wv);

    proj_kernel<<<dim3(8, 32, 3), 256>>>(bq, bk, bv);

    wmean_kernel<<<D / 32, 256>>>(Wo, bo);

    flash_kernel<<<dim3(8, 64), 256, FA_SMEM>>>(mask); // mt x bh

    final_kernel<<<M, 256>>>(out);
}

// round 11
// speedup vs baseline: 5.8165x; 1.5284x over previous
#include <cuda_runtime.h>
#include <cuda_bf16.h>
#include <mma.h>
#include <cstdint>
#include <cstddef>

using namespace nvcuda;

// Problem constants
constexpr int B  = 4;
constexpr int S  = 1024;
constexpr int D  = 1024;
constexpr int H  = 16;
constexpr int DK = 64;
constexpr int M  = B * S;          // 4096

constexpr int LDT = 72;            // smem stride for 64-wide tiles (pad 8) -> 144B rows

// Scratch (device globals; allocation-free per harness rules)
__device__ __align__(16) unsigned short g_qin[(size_t)M * D];   // bf16 inputs
__device__ __align__(16) unsigned short g_kin[(size_t)M * D];
__device__ __align__(16) unsigned short g_vin[(size_t)M * D];
__device__ __align__(16) unsigned short g_wq [(size_t)D * D];   // bf16 weights
__device__ __align__(16) unsigned short g_wk [(size_t)D * D];
__device__ __align__(16) unsigned short g_wv [(size_t)D * D];
__device__ __align__(16) unsigned short g_Qb[(size_t)M * D];    // bf16 projected
__device__ __align__(16) unsigned short g_Kb[(size_t)M * D];
__device__ __align__(16) unsigned short g_Vb[(size_t)M * D];
__device__ float d_Xt[(size_t)M * D];
__device__ float d_wmean[D];
__device__ float d_bmean;

// ---------------------------------------------------------------------------
__device__ __forceinline__ uint32_t smem_u32(const void* p) {
    uint32_t a;
    asm("{ .reg .u64 t; cvta.to.shared.u64 t, %1; cvt.u32.u64 %0, t; }" : "=r"(a) : "l"(p));
    return a;
}
#define CP_ASYNC16(dst, src) \
    asm volatile("cp.async.cg.shared.global [%0], [%1], 16;" :: "r"(dst), "l"(src) : "memory")
#define CP_COMMIT()  asm volatile("cp.async.commit_group;" ::: "memory")
#define CP_WAIT(n)   asm volatile("cp.async.wait_group %0;" :: "n"(n) : "memory")

#define LDSM_X4(r0, r1, r2, r3, a) \
    asm volatile("ldmatrix.sync.aligned.m8n8.x4.shared.b16 {%0,%1,%2,%3}, [%4];" \
                 : "=r"(r0), "=r"(r1), "=r"(r2), "=r"(r3) : "r"(a))
#define LDSM_X4_T(r0, r1, r2, r3, a) \
    asm volatile("ldmatrix.sync.aligned.m8n8.x4.trans.shared.b16 {%0,%1,%2,%3}, [%4];" \
                 : "=r"(r0), "=r"(r1), "=r"(r2), "=r"(r3) : "r"(a))
// D += A(bf16 m16k16) * B(bf16 k16n8), fp32 accum
#define MMA16816(d, a0, a1, a2, a3, b0, b1) \
    asm volatile("mma.sync.aligned.m16n8k16.row.col.f32.bf16.bf16.f32 " \
                 "{%0,%1,%2,%3}, {%4,%5,%6,%7}, {%8,%9}, {%0,%1,%2,%3};" \
                 : "+f"((d)[0]), "+f"((d)[1]), "+f"((d)[2]), "+f"((d)[3]) \
                 : "r"(a0), "r"(a1), "r"(a2), "r"(a3), "r"(b0), "r"(b1))

__device__ __forceinline__ uint32_t packbf2(float lo, float hi) {
    __nv_bfloat162 p = __float22bfloat162_rn(make_float2(lo, hi));
    return *(uint32_t*)&p;
}

// ---------------------------------------------------------------------------
// fp32 -> bf16 convert pass (unchanged from R9)
// ---------------------------------------------------------------------------
__global__ __launch_bounds__(256) void conv_kernel(
    const float* __restrict__ q,  const float* __restrict__ k,  const float* __restrict__ v,
    const float* __restrict__ wq, const float* __restrict__ wk, const float* __restrict__ wv)
{
    const int z = blockIdx.y;
    const float* src; unsigned short* dst; size_t n4;
    switch (z) {
        case 0: src = q;  dst = g_qin; n4 = (size_t)M * D / 4; break;
        case 1: src = k;  dst = g_kin; n4 = (size_t)M * D / 4; break;
        case 2: src = v;  dst = g_vin; n4 = (size_t)M * D / 4; break;
        case 3: src = wq; dst = g_wq;  n4 = (size_t)D * D / 4; break;
        case 4: src = wk; dst = g_wk;  n4 = (size_t)D * D / 4; break;
        default: src = wv; dst = g_wv; n4 = (size_t)D * D / 4; break;
    }
    for (size_t i = (size_t)blockIdx.x * 256 + threadIdx.x; i < n4;
         i += (size_t)gridDim.x * 256) {
        float4 f = ((const float4*)src)[i];
        uint2 o;
        o.x = packbf2(f.x, f.y);
        o.y = packbf2(f.z, f.w);
        ((uint2*)dst)[i] = o;
    }
}

// ---------------------------------------------------------------------------
// Fused QKV projection (unchanged from R9): grid (8, 32, 3), cp.async pipeline
// ---------------------------------------------------------------------------
__global__ __launch_bounds__(256) void proj_kernel(
    const float* __restrict__ bq, const float* __restrict__ bk,
    const float* __restrict__ bv)
{
    __shared__ __nv_bfloat16 sA[2][128 * LDT];
    __shared__ __nv_bfloat16 sB[2][128 * LDT];
    __shared__ float patch[8][256];

    const int t = threadIdx.x, wid = t >> 5, lane = t & 31;
    const int m0 = blockIdx.y * 128, n0 = blockIdx.x * 128;
    const int z  = blockIdx.z;
    const int wm = wid >> 2, wn = wid & 3;

    const unsigned short* Ain; const unsigned short* Wb;
    const float* bias; unsigned short* dst;
    switch (z) {
        case 0: Ain = g_qin; Wb = g_wq; bias = bq; dst = g_Qb; break;
        case 1: Ain = g_kin; Wb = g_wk; bias = bk; dst = g_Kb; break;
        default: Ain = g_vin; Wb = g_wv; bias = bv; dst = g_Vb; break;
    }
    const unsigned short* Asrc = Ain + (size_t)m0 * 1024;
    const unsigned short* Wsrc = Wb  + (size_t)n0 * 1024;

    const uint32_t uA = smem_u32(sA), uB = smem_u32(sB);
    constexpr uint32_t TILEB = 128 * LDT * 2;

    auto stage = [&](int k0, int buf) {
        #pragma unroll
        for (int i = t; i < 1024; i += 256) {
            int r = i >> 3, q = i & 7;
            CP_ASYNC16(uA + buf * TILEB + (uint32_t)(r * LDT + q * 8) * 2,
                       Asrc + (size_t)r * 1024 + k0 + q * 8);
        }
        #pragma unroll
        for (int i = t; i < 1024; i += 256) {
            int r = i >> 3, q = i & 7;
            CP_ASYNC16(uB + buf * TILEB + (uint32_t)(r * LDT + q * 8) * 2,
                       Wsrc + (size_t)r * 1024 + k0 + q * 8);
        }
        CP_COMMIT();
    };

    wmma::fragment<wmma::accumulator, 16, 16, 16, float> acc[4][2];
    #pragma unroll
    for (int i = 0; i < 4; i++)
        #pragma unroll
        for (int j = 0; j < 2; j++)
            wmma::fill_fragment(acc[i][j], 0.0f);

    stage(0, 0);

    for (int k0 = 0; k0 < 1024; k0 += 64) {
        const int buf = (k0 >> 6) & 1;
        if (k0 + 64 < 1024) {
            stage(k0 + 64, buf ^ 1);
            CP_WAIT(1);
        } else {
            CP_WAIT(0);
        }
        __syncthreads();

        #pragma unroll
        for (int ks = 0; ks < 4; ks++) {
            wmma::fragment<wmma::matrix_a, 16, 16, 16, __nv_bfloat16, wmma::row_major> af[4];
            wmma::fragment<wmma::matrix_b, 16, 16, 16, __nv_bfloat16, wmma::col_major> bf[2];
            #pragma unroll
            for (int i = 0; i < 4; i++)
                wmma::load_matrix_sync(af[i], sA[buf] + (wm * 64 + i * 16) * LDT + ks * 16, LDT);
            #pragma unroll
            for (int j = 0; j < 2; j++)
                wmma::load_matrix_sync(bf[j], sB[buf] + (wn * 32 + j * 16) * LDT + ks * 16, LDT);
            #pragma unroll
            for (int i = 0; i < 4; i++)
                #pragma unroll
                for (int j = 0; j < 2; j++)
                    wmma::mma_sync(acc[i][j], af[i], bf[j], acc[i][j]);
        }
        __syncthreads();
    }

    #pragma unroll
    for (int i = 0; i < 4; i++) {
        #pragma unroll
        for (int j = 0; j < 2; j++) {
            wmma::store_matrix_sync(patch[wid], acc[i][j], 16, wmma::mem_row_major);
            __syncwarp();
            int mbase = m0 + wm * 64 + i * 16;
            int nbase = n0 + wn * 32 + j * 16;
            #pragma unroll
            for (int q = 0; q < 4; q++) {
                int idx = lane * 8 + q * 2;
                int rr = idx >> 4, cc = idx & 15;
                int n = nbase + cc;
                float lo = patch[wid][idx]     + bias[n];
                float hi = patch[wid][idx + 1] + bias[n + 1];
                *(uint32_t*)&dst[(size_t)(mbase + rr) * 1024 + n] = packbf2(lo, hi);
            }
            __syncwarp();
        }
    }
}

// ---------------------------------------------------------------------------
// Flash attention v2: register-resident P, raw mma.sync m16n8k16.
// CTA = (q-tile mt: 128 rows, bh). 8 warps; warp w owns q-rows [16w,16w+16).
// Per k-tile (128 kpos): S = Q.K^T (16 n8-tiles), mask+exp in regs,
// pack to bf16 A-frags, O += P.V. K/V double-buffered via cp.async.
// Dynamic smem: sQ 0..18432 | sK0 ..36864 | sK1 ..55296 | sV0 ..73728 | sV1 ..92160
// ---------------------------------------------------------------------------
extern __shared__ char fa_smem[];

__global__ __launch_bounds__(256) void flash_kernel(const int* __restrict__ mask)
{
    const uint32_t uQ  = smem_u32(fa_smem);
    const uint32_t uK0 = uQ + 18432;
    const uint32_t uV0 = uQ + 55296;
    constexpr uint32_t TILEB = 18432;

    const int t = threadIdx.x, wid = t >> 5, lane = t & 31;
    const int mt = blockIdx.x, bh = blockIdx.y;
    const int b = bh >> 4, h = bh & 15;
    const int mrow = wid * 16;                  // warp's q-row base within tile
    const int g = lane >> 2, qtid = lane & 3;   // quad coords
    const int qrow0 = mt * 128;

    // ldmatrix per-lane address components
    const int x4row = (lane & 7) + ((lane >> 3) & 1) * 8;   // Q/V pattern
    const int x4col = (lane >> 4) * 8;
    const int krow  = lane & 7;                              // K pattern
    const int kcol  = (lane >> 3) * 8;

    const unsigned short* Ksrc = g_Kb + ((size_t)(b * 1024)) * 1024 + h * 64;
    const unsigned short* Vsrc = g_Vb + ((size_t)(b * 1024)) * 1024 + h * 64;

    // stage K/V k-tile kt into buffer buf
    auto stage = [&](int kt, int buf) {
        const unsigned short* ks = Ksrc + (size_t)(kt * 128) * 1024;
        const unsigned short* vs = Vsrc + (size_t)(kt * 128) * 1024;
        #pragma unroll
        for (int i = t; i < 1024; i += 256) {
            int r = i >> 3, q = i & 7;
            CP_ASYNC16(uK0 + buf * TILEB + (uint32_t)(r * LDT + q * 8) * 2,
                       ks + (size_t)r * 1024 + q * 8);
        }
        #pragma unroll
        for (int i = t; i < 1024; i += 256) {
            int r = i >> 3, q = i & 7;
            CP_ASYNC16(uV0 + buf * TILEB + (uint32_t)(r * LDT + q * 8) * 2,
                       vs + (size_t)r * 1024 + q * 8);
        }
        CP_COMMIT();
    };

    // kick off K/V for kt=0, then load Q (plain) and preload Q a-frags
    stage(0, 0);

    const unsigned short* Qsrc = g_Qb + ((size_t)(b * 1024 + qrow0)) * 1024 + h * 64;
    #pragma unroll
    for (int i = t; i < 1024; i += 256) {
        int r = i >> 3, q = i & 7;
        uint4 v = *(const uint4*)(Qsrc + (size_t)r * 1024 + q * 8);
        uint32_t a = uQ + (uint32_t)(r * LDT + q * 8) * 2;
        asm volatile("st.shared.v4.b32 [%0], {%1,%2,%3,%4};"
                     :: "r"(a), "r"(v.x), "r"(v.y), "r"(v.z), "r"(v.w) : "memory");
    }
    __syncthreads();

    uint32_t qa[4][4];                          // a-frags: 4 ksteps (dk)
    #pragma unroll
    for (int ks = 0; ks < 4; ks++) {
        uint32_t a = uQ + (uint32_t)((mrow + x4row) * LDT + ks * 16 + x4col) * 2;
        LDSM_X4(qa[ks][0], qa[ks][1], qa[ks][2], qa[ks][3], a);
    }

    float oacc[8][4];                           // O: 8 n8-tiles over dk=64
    #pragma unroll
    for (int n = 0; n < 8; n++)
        #pragma unroll
        for (int c = 0; c < 4; c++) oacc[n][c] = 0.0f;

    float l0 = 0.0f, l1 = 0.0f;                 // row-sum partials (rows g, g+8)

    const int* mbase = mask + ((size_t)b << 20);
    const int qg = qrow0 + mrow + g;            // this thread's q-row (quad row)

    for (int kt = 0; kt < 8; kt++) {
        const int buf = kt & 1;
        if (kt < 7) { stage(kt + 1, buf ^ 1); CP_WAIT(1); }
        else        { CP_WAIT(0); }
        __syncthreads();

        const uint32_t uK = uK0 + buf * TILEB;
        const uint32_t uV = uV0 + buf * TILEB;

        #pragma unroll
        for (int jp = 0; jp < 8; jp++) {        // pairs of n8 S-tiles = one k16 chunk
            // mask for both tiles of the pair, both quad rows
            const int colg = kt * 128 + jp * 16 + qtid * 2;
            int2 mk00 = *(const int2*)(mbase + (size_t)qg       * 1024 + colg);
            int2 mk01 = *(const int2*)(mbase + (size_t)(qg + 8) * 1024 + colg);
            int2 mk10 = *(const int2*)(mbase + (size_t)qg       * 1024 + colg + 8);
            int2 mk11 = *(const int2*)(mbase + (size_t)(qg + 8) * 1024 + colg + 8);

            float sc0[4] = {0, 0, 0, 0}, sc1[4] = {0, 0, 0, 0};
            // S-MMA: tiles j0 = 2*jp, j1 = 2*jp+1, over dk (4 ksteps)
            {
                uint32_t k0, k1, k2, k3;
                uint32_t a0 = uK + (uint32_t)((jp * 16 + krow) * LDT + kcol) * 2;
                LDSM_X4(k0, k1, k2, k3, a0);
                MMA16816(sc0, qa[0][0], qa[0][1], qa[0][2], qa[0][3], k0, k1);
                MMA16816(sc0, qa[1][0], qa[1][1], qa[1][2], qa[1][3], k2, k3);
                uint32_t a1 = uK + (uint32_t)((jp * 16 + krow) * LDT + 32 + kcol) * 2;
                LDSM_X4(k0, k1, k2, k3, a1);
                MMA16816(sc0, qa[2][0], qa[2][1], qa[2][2], qa[2][3], k0, k1);
                MMA16816(sc0, qa[3][0], qa[3][1], qa[3][2], qa[3][3], k2, k3);

                uint32_t a2 = uK + (uint32_t)((jp * 16 + 8 + krow) * LDT + kcol) * 2;
                LDSM_X4(k0, k1, k2, k3, a2);
                MMA16816(sc1, qa[0][0], qa[0][1], qa[0][2], qa[0][3], k0, k1);
                MMA16816(sc1, qa[1][0], qa[1][1], qa[1][2], qa[1][3], k2, k3);
                uint32_t a3 = uK + (uint32_t)((jp * 16 + 8 + krow) * LDT + 32 + kcol) * 2;
                LDSM_X4(k0, k1, k2, k3, a3);
                MMA16816(sc1, qa[2][0], qa[2][1], qa[2][2], qa[2][3], k0, k1);
                MMA16816(sc1, qa[3][0], qa[3][1], qa[3][2], qa[3][3], k2, k3);
            }

            // mask, scale, exp (in registers)
            float e00 = (mk00.x == 0) ? -1e9f : sc0[0] * 0.125f;
            float e01 = (mk00.y == 0) ? -1e9f : sc0[1] * 0.125f;
            float e02 = (mk01.x == 0) ? -1e9f : sc0[2] * 0.125f;
            float e03 = (mk01.y == 0) ? -1e9f : sc0[3] * 0.125f;
            float e10 = (mk10.x == 0) ? -1e9f : sc1[0] * 0.125f;
            float e11 = (mk10.y == 0) ? -1e9f : sc1[1] * 0.125f;
            float e12 = (mk11.x == 0) ? -1e9f : sc1[2] * 0.125f;
            float e13 = (mk11.y == 0) ? -1e9f : sc1[3] * 0.125f;
            e00 = __expf(fmaxf(e00, -30.0f)); e01 = __expf(fmaxf(e01, -30.0f));
            e02 = __expf(fmaxf(e02, -30.0f)); e03 = __expf(fmaxf(e03, -30.0f));
            e10 = __expf(fmaxf(e10, -30.0f)); e11 = __expf(fmaxf(e11, -30.0f));
            e12 = __expf(fmaxf(e12, -30.0f)); e13 = __expf(fmaxf(e13, -30.0f));

            l0 += e00 + e01 + e10 + e11;        // row g
            l1 += e02 + e03 + e12 + e13;        // row g+8

            // pack P a-frag (m16 x k16): tiles (j0 -> k 0-7, j1 -> k 8-15)
            uint32_t pa0 = packbf2(e00, e01);   // row g,   k 0-7
            uint32_t pa1 = packbf2(e02, e03);   // row g+8, k 0-7
            uint32_t pa2 = packbf2(e10, e11);   // row g,   k 8-15
            uint32_t pa3 = packbf2(e12, e13);   // row g+8, k 8-15

            // O += P . V  (kstep = jp; 8 dk n8-tiles via 4 x4.trans loads)
            #pragma unroll
            for (int dkp = 0; dkp < 4; dkp++) {
                uint32_t v0, v1, v2, v3;
                uint32_t a = uV + (uint32_t)((jp * 16 + x4row) * LDT + dkp * 16 + x4col) * 2;
                LDSM_X4_T(v0, v1, v2, v3, a);
                MMA16816(oacc[2 * dkp],     pa0, pa1, pa2, pa3, v0, v1);
                MMA16816(oacc[2 * dkp + 1], pa0, pa1, pa2, pa3, v2, v3);
            }
        }
        __syncthreads();
    }

    // full row sums across the quad
    #pragma unroll
    for (int o = 1; o < 4; o <<= 1) {
        l0 += __shfl_xor_sync(0xffffffffu, l0, o);
        l1 += __shfl_xor_sync(0xffffffffu, l1, o);
    }
    const float inv0 = 1.0f / l0, inv1 = 1.0f / l1;

    // epilogue: normalize, threshold, write fp32
    #pragma unroll
    for (int n = 0; n < 8; n++) {
        int col = h * 64 + n * 8 + qtid * 2;
        float v0 = oacc[n][0] * inv0, v1 = oacc[n][1] * inv0;
        float v2 = oacc[n][2] * inv1, v3 = oacc[n][3] * inv1;
        v0 = (v0 > 0.2f) ? v0 : 0.0f;
        v1 = (v1 > 0.2f) ? v1 : 0.0f;
        v2 = (v2 > 0.2f) ? v2 : 0.0f;
        v3 = (v3 > 0.2f) ? v3 : 0.0f;
        *(float2*)&d_Xt[((size_t)b * 1024 + qg)     * 1024 + col] = make_float2(v0, v1);
        *(float2*)&d_Xt[((size_t)b * 1024 + qg + 8) * 1024 + col] = make_float2(v2, v3);
    }
}

// ---------------------------------------------------------------------------
// Column means of Wo (and mean of bo)
// ---------------------------------------------------------------------------
__global__ __launch_bounds__(256) void wmean_kernel(const float* __restrict__ Wo,
                                                    const float* __restrict__ bo)
{
    __shared__ float sred[256];

    const int t    = threadIdx.x;
    const int col  = blockIdx.x * 32 + (t & 31);
    const int part = t >> 5;

    float s = 0.0f;
    const int nlo = part * 128, nhi = nlo + 128;
    for (int n = nlo; n < nhi; n++) s += Wo[(size_t)n * D + col];
    sred[t] = s;
    __syncthreads();

    if (part == 0) {
        float tot = 0.0f;
        #pragma unroll
        for (int p = 0; p < 8; p++) tot += sred[p * 32 + (t & 31)];
        d_wmean[col] = tot * (1.0f / D);
    }
    __syncthreads();

    if (blockIdx.x == 0) {
        float sb = 0.0f;
        #pragma unroll
        for (int i = t; i < D; i += 256) sb += bo[i];
        #pragma unroll
        for (int o = 16; o > 0; o >>= 1) sb += __shfl_xor_sync(0xffffffffu, sb, o);
        if ((t & 31) == 0) sred[t >> 5] = sb;
        __syncthreads();
        if (t == 0) {
            float x = 0.0f;
            #pragma unroll
            for (int p = 0; p < 8; p++) x += sred[p];
            d_bmean = x * (1.0f / D);
        }
    }
}

// ---------------------------------------------------------------------------
// Final: out[r,:] = Xt[r,:] + (Xt[r,:] . wmean + bmean)
// ---------------------------------------------------------------------------
__global__ __launch_bounds__(256) void final_kernel(float* __restrict__ out)
{
    __shared__ float red[8];
    __shared__ float bc;

    const size_t row = blockIdx.x;
    const float* x = d_Xt + row * D;
    const int t = threadIdx.x;

    float partial = 0.0f;
    #pragma unroll
    for (int dd = 0; dd < 4; dd++) {
        int idx = t + dd * 256;
        partial += x[idx] * d_wmean[idx];
    }
    #pragma unroll
    for (int o = 16; o > 0; o >>= 1) partial += __shfl_xor_sync(0xffffffffu, partial, o);
    if ((t & 31) == 0) red[t >> 5] = partial;
    __syncthreads();
    if (t < 8) {
        float s = red[t];
        #pragma unroll
        for (int o = 4; o > 0; o >>= 1) s += __shfl_xor_sync(0xffu, s, o);
        if (t == 0) bc = s + d_bmean;
    }
    __syncthreads();
    float scalar = bc;

    #pragma unroll
    for (int dd = 0; dd < 4; dd++) {
        int idx = t + dd * 256;
        out[row * D + idx] = x[idx] + scalar;
    }
}

// ---------------------------------------------------------------------------
extern "C" void kernel_launch(void* const* d_in, const int* in_sizes, int n_in,
                              void* d_out, int out_size)
{
    const float* query = (const float*)d_in[0];
    const float* key_  = (const float*)d_in[1];
    const float* value = (const float*)d_in[2];
    const int*   mask  = (const int*)  d_in[3];
    const float* Wq    = (const float*)d_in[4];
    const float* bq    = (const float*)d_in[5];
    const float* Wk    = (const float*)d_in[6];
    const float* bk    = (const float*)d_in[7];
    const float* Wv    = (const float*)d_in[8];
    const float* bv    = (const float*)d_in[9];
    const float* Wo    = (const float*)d_in[10];
    const float* bo    = (const float*)d_in[11];
    float* out = (float*)d_out;

    constexpr int FA_SMEM = 92160;
    cudaFuncSetAttribute(flash_kernel, cudaFuncAttributeMaxDynamicSharedMemorySize, FA_SMEM);

    conv_kernel<<<dim3(256, 6), 256>>>(query, key_, value, Wq, Wk, Wv);

    proj_kernel<<<dim3(8, 32, 3), 256>>>(bq, bk, bv);

    wmean_kernel<<<D / 32, 256>>>(Wo, bo);

    flash_kernel<<<dim3(8, 64), 256, FA_SMEM>>>(mask); // mt x bh

    final_kernel<<<M, 256>>>(out);
}

// round 12
// speedup vs baseline: 6.5539x; 1.1268x over previous
#include <cuda_runtime.h>
#include <cuda_bf16.h>
#include <mma.h>
#include <cstdint>
#include <cstddef>

using namespace nvcuda;

// Problem constants
constexpr int B  = 4;
constexpr int S  = 1024;
constexpr int D  = 1024;
constexpr int H  = 16;
constexpr int DK = 64;
constexpr int M  = B * S;          // 4096

constexpr int LDT = 72;            // smem stride for 64-wide tiles (pad 8) -> 144B rows

// Scratch (device globals; allocation-free per harness rules)
__device__ __align__(16) unsigned short g_qin[(size_t)M * D];   // bf16 inputs
__device__ __align__(16) unsigned short g_kin[(size_t)M * D];
__device__ __align__(16) unsigned short g_vin[(size_t)M * D];
__device__ __align__(16) unsigned short g_wq [(size_t)D * D];   // bf16 weights
__device__ __align__(16) unsigned short g_wk [(size_t)D * D];
__device__ __align__(16) unsigned short g_wv [(size_t)D * D];
__device__ __align__(16) unsigned short g_Qb[(size_t)M * D];    // bf16 projected
__device__ __align__(16) unsigned short g_Kb[(size_t)M * D];
__device__ __align__(16) unsigned short g_Vb[(size_t)M * D];
__device__ __align__(16) unsigned int g_mbits[(size_t)M * 32];  // packed mask bits
__device__ float d_Xt[(size_t)M * D];
__device__ float d_wmean[D];
__device__ float d_bmean;

// ---------------------------------------------------------------------------
__device__ __forceinline__ uint32_t smem_u32(const void* p) {
    uint32_t a;
    asm("{ .reg .u64 t; cvta.to.shared.u64 t, %1; cvt.u32.u64 %0, t; }" : "=r"(a) : "l"(p));
    return a;
}
#define CP_ASYNC16(dst, src) \
    asm volatile("cp.async.cg.shared.global [%0], [%1], 16;" :: "r"(dst), "l"(src) : "memory")
#define CP_COMMIT()  asm volatile("cp.async.commit_group;" ::: "memory")
#define CP_WAIT(n)   asm volatile("cp.async.wait_group %0;" :: "n"(n) : "memory")

#define LDSM_X4(r0, r1, r2, r3, a) \
    asm volatile("ldmatrix.sync.aligned.m8n8.x4.shared.b16 {%0,%1,%2,%3}, [%4];" \
                 : "=r"(r0), "=r"(r1), "=r"(r2), "=r"(r3) : "r"(a))
#define LDSM_X4_T(r0, r1, r2, r3, a) \
    asm volatile("ldmatrix.sync.aligned.m8n8.x4.trans.shared.b16 {%0,%1,%2,%3}, [%4];" \
                 : "=r"(r0), "=r"(r1), "=r"(r2), "=r"(r3) : "r"(a))
#define MMA16816(d, a0, a1, a2, a3, b0, b1) \
    asm volatile("mma.sync.aligned.m16n8k16.row.col.f32.bf16.bf16.f32 " \
                 "{%0,%1,%2,%3}, {%4,%5,%6,%7}, {%8,%9}, {%0,%1,%2,%3};" \
                 : "+f"((d)[0]), "+f"((d)[1]), "+f"((d)[2]), "+f"((d)[3]) \
                 : "r"(a0), "r"(a1), "r"(a2), "r"(a3), "r"(b0), "r"(b1))

__device__ __forceinline__ uint32_t packbf2(float lo, float hi) {
    __nv_bfloat162 p = __float22bfloat162_rn(make_float2(lo, hi));
    return *(uint32_t*)&p;
}

// ---------------------------------------------------------------------------
// fp32 -> bf16 convert pass
// ---------------------------------------------------------------------------
__global__ __launch_bounds__(256) void conv_kernel(
    const float* __restrict__ q,  const float* __restrict__ k,  const float* __restrict__ v,
    const float* __restrict__ wq, const float* __restrict__ wk, const float* __restrict__ wv)
{
    const int z = blockIdx.y;
    const float* src; unsigned short* dst; size_t n4;
    switch (z) {
        case 0: src = q;  dst = g_qin; n4 = (size_t)M * D / 4; break;
        case 1: src = k;  dst = g_kin; n4 = (size_t)M * D / 4; break;
        case 2: src = v;  dst = g_vin; n4 = (size_t)M * D / 4; break;
        case 3: src = wq; dst = g_wq;  n4 = (size_t)D * D / 4; break;
        case 4: src = wk; dst = g_wk;  n4 = (size_t)D * D / 4; break;
        default: src = wv; dst = g_wv; n4 = (size_t)D * D / 4; break;
    }
    for (size_t i = (size_t)blockIdx.x * 256 + threadIdx.x; i < n4;
         i += (size_t)gridDim.x * 256) {
        float4 f = ((const float4*)src)[i];
        uint2 o;
        o.x = packbf2(f.x, f.y);
        o.y = packbf2(f.z, f.w);
        ((uint2*)dst)[i] = o;
    }
}

// ---------------------------------------------------------------------------
// Pack mask int32 -> bits. One warp per global row (b*1024+row).
// bit c&31 of word (row, c>>5) = (mask[row][c] != 0)
// ---------------------------------------------------------------------------
__global__ __launch_bounds__(256) void maskpack_kernel(const int* __restrict__ mask)
{
    const int row  = blockIdx.x * 8 + (threadIdx.x >> 5);
    const int lane = threadIdx.x & 31;
    const int* src = mask + (size_t)row * 1024;
    #pragma unroll
    for (int w = 0; w < 32; w++) {
        int v = src[w * 32 + lane];
        uint32_t bits = __ballot_sync(0xffffffffu, v != 0);
        if (lane == 0) g_mbits[(size_t)row * 32 + w] = bits;
    }
}

// ---------------------------------------------------------------------------
// Fused QKV projection (unchanged): grid (8, 32, 3), cp.async pipeline
// ---------------------------------------------------------------------------
__global__ __launch_bounds__(256) void proj_kernel(
    const float* __restrict__ bq, const float* __restrict__ bk,
    const float* __restrict__ bv)
{
    __shared__ __nv_bfloat16 sA[2][128 * LDT];
    __shared__ __nv_bfloat16 sB[2][128 * LDT];
    __shared__ float patch[8][256];

    const int t = threadIdx.x, wid = t >> 5, lane = t & 31;
    const int m0 = blockIdx.y * 128, n0 = blockIdx.x * 128;
    const int z  = blockIdx.z;
    const int wm = wid >> 2, wn = wid & 3;

    const unsigned short* Ain; const unsigned short* Wb;
    const float* bias; unsigned short* dst;
    switch (z) {
        case 0: Ain = g_qin; Wb = g_wq; bias = bq; dst = g_Qb; break;
        case 1: Ain = g_kin; Wb = g_wk; bias = bk; dst = g_Kb; break;
        default: Ain = g_vin; Wb = g_wv; bias = bv; dst = g_Vb; break;
    }
    const unsigned short* Asrc = Ain + (size_t)m0 * 1024;
    const unsigned short* Wsrc = Wb  + (size_t)n0 * 1024;

    const uint32_t uA = smem_u32(sA), uB = smem_u32(sB);
    constexpr uint32_t TILEB = 128 * LDT * 2;

    auto stage = [&](int k0, int buf) {
        #pragma unroll
        for (int i = t; i < 1024; i += 256) {
            int r = i >> 3, q = i & 7;
            CP_ASYNC16(uA + buf * TILEB + (uint32_t)(r * LDT + q * 8) * 2,
                       Asrc + (size_t)r * 1024 + k0 + q * 8);
        }
        #pragma unroll
        for (int i = t; i < 1024; i += 256) {
            int r = i >> 3, q = i & 7;
            CP_ASYNC16(uB + buf * TILEB + (uint32_t)(r * LDT + q * 8) * 2,
                       Wsrc + (size_t)r * 1024 + k0 + q * 8);
        }
        CP_COMMIT();
    };

    wmma::fragment<wmma::accumulator, 16, 16, 16, float> acc[4][2];
    #pragma unroll
    for (int i = 0; i < 4; i++)
        #pragma unroll
        for (int j = 0; j < 2; j++)
            wmma::fill_fragment(acc[i][j], 0.0f);

    stage(0, 0);

    for (int k0 = 0; k0 < 1024; k0 += 64) {
        const int buf = (k0 >> 6) & 1;
        if (k0 + 64 < 1024) {
            stage(k0 + 64, buf ^ 1);
            CP_WAIT(1);
        } else {
            CP_WAIT(0);
        }
        __syncthreads();

        #pragma unroll
        for (int ks = 0; ks < 4; ks++) {
            wmma::fragment<wmma::matrix_a, 16, 16, 16, __nv_bfloat16, wmma::row_major> af[4];
            wmma::fragment<wmma::matrix_b, 16, 16, 16, __nv_bfloat16, wmma::col_major> bf[2];
            #pragma unroll
            for (int i = 0; i < 4; i++)
                wmma::load_matrix_sync(af[i], sA[buf] + (wm * 64 + i * 16) * LDT + ks * 16, LDT);
            #pragma unroll
            for (int j = 0; j < 2; j++)
                wmma::load_matrix_sync(bf[j], sB[buf] + (wn * 32 + j * 16) * LDT + ks * 16, LDT);
            #pragma unroll
            for (int i = 0; i < 4; i++)
                #pragma unroll
                for (int j = 0; j < 2; j++)
                    wmma::mma_sync(acc[i][j], af[i], bf[j], acc[i][j]);
        }
        __syncthreads();
    }

    #pragma unroll
    for (int i = 0; i < 4; i++) {
        #pragma unroll
        for (int j = 0; j < 2; j++) {
            wmma::store_matrix_sync(patch[wid], acc[i][j], 16, wmma::mem_row_major);
            __syncwarp();
            int mbase = m0 + wm * 64 + i * 16;
            int nbase = n0 + wn * 32 + j * 16;
            #pragma unroll
            for (int q = 0; q < 4; q++) {
                int idx = lane * 8 + q * 2;
                int rr = idx >> 4, cc = idx & 15;
                int n = nbase + cc;
                float lo = patch[wid][idx]     + bias[n];
                float hi = patch[wid][idx + 1] + bias[n + 1];
                *(uint32_t*)&dst[(size_t)(mbase + rr) * 1024 + n] = packbf2(lo, hi);
            }
            __syncwarp();
        }
    }
}

// ---------------------------------------------------------------------------
// Flash attention v2, 32 q-rows per warp. CTA = 256 q-rows x bh; grid (4, 64).
// Warp w owns rows [32w, 32w+32) as two m16 row blocks. K/V ldmatrix results
// feed both row blocks (halved smem traffic). Mask via packed bits.
// smem: sQ 0..36864 | sK (2 bufs) ..73728 | sV (2 bufs) ..110592
// ---------------------------------------------------------------------------
extern __shared__ char fa_smem[];

__global__ __launch_bounds__(256) void flash_kernel()
{
    const uint32_t uQ  = smem_u32(fa_smem);
    const uint32_t uK0 = uQ + 36864;
    const uint32_t uV0 = uQ + 73728;
    constexpr uint32_t TILEB = 18432;

    const int t = threadIdx.x, wid = t >> 5, lane = t & 31;
    const int mt = blockIdx.x, bh = blockIdx.y;
    const int b = bh >> 4, h = bh & 15;
    const int g = lane >> 2, qtid = lane & 3;
    const int qrow0 = mt * 256;

    const int x4row = (lane & 7) + ((lane >> 3) & 1) * 8;
    const int x4col = (lane >> 4) * 8;
    const int krow  = lane & 7;
    const int kcol  = (lane >> 3) * 8;

    const unsigned short* Ksrc = g_Kb + ((size_t)(b * 1024)) * 1024 + h * 64;
    const unsigned short* Vsrc = g_Vb + ((size_t)(b * 1024)) * 1024 + h * 64;

    auto stage = [&](int kt, int buf) {
        const unsigned short* ks = Ksrc + (size_t)(kt * 128) * 1024;
        const unsigned short* vs = Vsrc + (size_t)(kt * 128) * 1024;
        #pragma unroll
        for (int i = t; i < 1024; i += 256) {
            int r = i >> 3, q = i & 7;
            CP_ASYNC16(uK0 + buf * TILEB + (uint32_t)(r * LDT + q * 8) * 2,
                       ks + (size_t)r * 1024 + q * 8);
        }
        #pragma unroll
        for (int i = t; i < 1024; i += 256) {
            int r = i >> 3, q = i & 7;
            CP_ASYNC16(uV0 + buf * TILEB + (uint32_t)(r * LDT + q * 8) * 2,
                       vs + (size_t)r * 1024 + q * 8);
        }
        CP_COMMIT();
    };

    stage(0, 0);

    // Q tile: 256 rows x 64
    const unsigned short* Qsrc = g_Qb + ((size_t)(b * 1024 + qrow0)) * 1024 + h * 64;
    #pragma unroll
    for (int i = t; i < 2048; i += 256) {
        int r = i >> 3, q = i & 7;
        uint4 v = *(const uint4*)(Qsrc + (size_t)r * 1024 + q * 8);
        uint32_t a = uQ + (uint32_t)(r * LDT + q * 8) * 2;
        asm volatile("st.shared.v4.b32 [%0], {%1,%2,%3,%4};"
                     :: "r"(a), "r"(v.x), "r"(v.y), "r"(v.z), "r"(v.w) : "memory");
    }
    __syncthreads();

    uint32_t qa[2][4][4];                       // [row block][kstep][frag]
    #pragma unroll
    for (int r = 0; r < 2; r++)
        #pragma unroll
        for (int ks = 0; ks < 4; ks++) {
            uint32_t a = uQ + (uint32_t)((wid * 32 + r * 16 + x4row) * LDT + ks * 16 + x4col) * 2;
            LDSM_X4(qa[r][ks][0], qa[r][ks][1], qa[r][ks][2], qa[r][ks][3], a);
        }

    float oacc[2][8][4];
    #pragma unroll
    for (int r = 0; r < 2; r++)
        #pragma unroll
        for (int n = 0; n < 8; n++)
            #pragma unroll
            for (int c = 0; c < 4; c++) oacc[r][n][c] = 0.0f;

    float lsum[2][2] = {{0, 0}, {0, 0}};        // [row block][g row / g+8 row]

    const int rg0 = b * 1024 + qrow0 + wid * 32 + g;   // global row (block 0, quad row g)
    const uint4* mb = (const uint4*)g_mbits;

    for (int kt = 0; kt < 8; kt++) {
        const int buf = kt & 1;
        if (kt < 7) { stage(kt + 1, buf ^ 1); CP_WAIT(1); }
        else        { CP_WAIT(0); }
        __syncthreads();

        const uint32_t uK = uK0 + buf * TILEB;
        const uint32_t uV = uV0 + buf * TILEB;

        // packed mask words for this k-tile: 4 rows of interest
        uint4 mw[4];
        mw[0] = mb[(size_t)rg0 * 8 + kt];              // block 0, row g
        mw[1] = mb[(size_t)(rg0 + 8) * 8 + kt];        // block 0, row g+8
        mw[2] = mb[(size_t)(rg0 + 16) * 8 + kt];       // block 1, row g
        mw[3] = mb[(size_t)(rg0 + 24) * 8 + kt];       // block 1, row g+8

        #pragma unroll
        for (int jp = 0; jp < 8; jp++) {
            float s00[4] = {0, 0, 0, 0};   // n8 tile 0, row block 0
            float s01[4] = {0, 0, 0, 0};   // n8 tile 0, row block 1
            float s10[4] = {0, 0, 0, 0};   // n8 tile 1, row block 0
            float s11[4] = {0, 0, 0, 0};   // n8 tile 1, row block 1

            {
                uint32_t k0, k1, k2, k3;
                uint32_t a0 = uK + (uint32_t)((jp * 16 + krow) * LDT + kcol) * 2;
                LDSM_X4(k0, k1, k2, k3, a0);
                MMA16816(s00, qa[0][0][0], qa[0][0][1], qa[0][0][2], qa[0][0][3], k0, k1);
                MMA16816(s00, qa[0][1][0], qa[0][1][1], qa[0][1][2], qa[0][1][3], k2, k3);
                MMA16816(s01, qa[1][0][0], qa[1][0][1], qa[1][0][2], qa[1][0][3], k0, k1);
                MMA16816(s01, qa[1][1][0], qa[1][1][1], qa[1][1][2], qa[1][1][3], k2, k3);
                uint32_t a1 = uK + (uint32_t)((jp * 16 + krow) * LDT + 32 + kcol) * 2;
                LDSM_X4(k0, k1, k2, k3, a1);
                MMA16816(s00, qa[0][2][0], qa[0][2][1], qa[0][2][2], qa[0][2][3], k0, k1);
                MMA16816(s00, qa[0][3][0], qa[0][3][1], qa[0][3][2], qa[0][3][3], k2, k3);
                MMA16816(s01, qa[1][2][0], qa[1][2][1], qa[1][2][2], qa[1][2][3], k0, k1);
                MMA16816(s01, qa[1][3][0], qa[1][3][1], qa[1][3][2], qa[1][3][3], k2, k3);
                uint32_t a2 = uK + (uint32_t)((jp * 16 + 8 + krow) * LDT + kcol) * 2;
                LDSM_X4(k0, k1, k2, k3, a2);
                MMA16816(s10, qa[0][0][0], qa[0][0][1], qa[0][0][2], qa[0][0][3], k0, k1);
                MMA16816(s10, qa[0][1][0], qa[0][1][1], qa[0][1][2], qa[0][1][3], k2, k3);
                MMA16816(s11, qa[1][0][0], qa[1][0][1], qa[1][0][2], qa[1][0][3], k0, k1);
                MMA16816(s11, qa[1][1][0], qa[1][1][1], qa[1][1][2], qa[1][1][3], k2, k3);
                uint32_t a3 = uK + (uint32_t)((jp * 16 + 8 + krow) * LDT + 32 + kcol) * 2;
                LDSM_X4(k0, k1, k2, k3, a3);
                MMA16816(s10, qa[0][2][0], qa[0][2][1], qa[0][2][2], qa[0][2][3], k0, k1);
                MMA16816(s10, qa[0][3][0], qa[0][3][1], qa[0][3][2], qa[0][3][3], k2, k3);
                MMA16816(s11, qa[1][2][0], qa[1][2][1], qa[1][2][2], qa[1][2][3], k0, k1);
                MMA16816(s11, qa[1][3][0], qa[1][3][1], qa[1][3][2], qa[1][3][3], k2, k3);
            }

            const int sft = (jp & 1) * 16 + qtid * 2;
            uint32_t pa[2][4];

            #pragma unroll
            for (int r = 0; r < 2; r++) {
                uint32_t wA = (&mw[2 * r].x)[jp >> 1];       // row g
                uint32_t wB = (&mw[2 * r + 1].x)[jp >> 1];   // row g+8
                float* t0 = (r == 0) ? s00 : s01;
                float* t1 = (r == 0) ? s10 : s11;

                float e00 = ((wA >> sft)       & 1) ? t0[0] * 0.125f : -1e9f;
                float e01 = ((wA >> (sft + 1)) & 1) ? t0[1] * 0.125f : -1e9f;
                float e02 = ((wB >> sft)       & 1) ? t0[2] * 0.125f : -1e9f;
                float e03 = ((wB >> (sft + 1)) & 1) ? t0[3] * 0.125f : -1e9f;
                float e10 = ((wA >> (sft + 8)) & 1) ? t1[0] * 0.125f : -1e9f;
                float e11 = ((wA >> (sft + 9)) & 1) ? t1[1] * 0.125f : -1e9f;
                float e12 = ((wB >> (sft + 8)) & 1) ? t1[2] * 0.125f : -1e9f;
                float e13 = ((wB >> (sft + 9)) & 1) ? t1[3] * 0.125f : -1e9f;

                e00 = __expf(fmaxf(e00, -30.0f)); e01 = __expf(fmaxf(e01, -30.0f));
                e02 = __expf(fmaxf(e02, -30.0f)); e03 = __expf(fmaxf(e03, -30.0f));
                e10 = __expf(fmaxf(e10, -30.0f)); e11 = __expf(fmaxf(e11, -30.0f));
                e12 = __expf(fmaxf(e12, -30.0f)); e13 = __expf(fmaxf(e13, -30.0f));

                lsum[r][0] += e00 + e01 + e10 + e11;
                lsum[r][1] += e02 + e03 + e12 + e13;

                pa[r][0] = packbf2(e00, e01);
                pa[r][1] = packbf2(e02, e03);
                pa[r][2] = packbf2(e10, e11);
                pa[r][3] = packbf2(e12, e13);
            }

            #pragma unroll
            for (int dkp = 0; dkp < 4; dkp++) {
                uint32_t v0, v1, v2, v3;
                uint32_t a = uV + (uint32_t)((jp * 16 + x4row) * LDT + dkp * 16 + x4col) * 2;
                LDSM_X4_T(v0, v1, v2, v3, a);
                MMA16816(oacc[0][2 * dkp],     pa[0][0], pa[0][1], pa[0][2], pa[0][3], v0, v1);
                MMA16816(oacc[0][2 * dkp + 1], pa[0][0], pa[0][1], pa[0][2], pa[0][3], v2, v3);
                MMA16816(oacc[1][2 * dkp],     pa[1][0], pa[1][1], pa[1][2], pa[1][3], v0, v1);
                MMA16816(oacc[1][2 * dkp + 1], pa[1][0], pa[1][1], pa[1][2], pa[1][3], v2, v3);
            }
        }
        __syncthreads();
    }

    // row sums across quads
    #pragma unroll
    for (int r = 0; r < 2; r++)
        #pragma unroll
        for (int o = 1; o < 4; o <<= 1) {
            lsum[r][0] += __shfl_xor_sync(0xffffffffu, lsum[r][0], o);
            lsum[r][1] += __shfl_xor_sync(0xffffffffu, lsum[r][1], o);
        }

    // epilogue: normalize, threshold, write fp32
    #pragma unroll
    for (int r = 0; r < 2; r++) {
        const float inv0 = 1.0f / lsum[r][0], inv1 = 1.0f / lsum[r][1];
        const size_t row0 = (size_t)rg0 + 16 * r;        // global row (incl. batch)
        #pragma unroll
        for (int n = 0; n < 8; n++) {
            int col = h * 64 + n * 8 + qtid * 2;
            float v0 = oacc[r][n][0] * inv0, v1 = oacc[r][n][1] * inv0;
            float v2 = oacc[r][n][2] * inv1, v3 = oacc[r][n][3] * inv1;
            v0 = (v0 > 0.2f) ? v0 : 0.0f;
            v1 = (v1 > 0.2f) ? v1 : 0.0f;
            v2 = (v2 > 0.2f) ? v2 : 0.0f;
            v3 = (v3 > 0.2f) ? v3 : 0.0f;
            *(float2*)&d_Xt[row0 * 1024 + col]       = make_float2(v0, v1);
            *(float2*)&d_Xt[(row0 + 8) * 1024 + col] = make_float2(v2, v3);
        }
    }
}

// ---------------------------------------------------------------------------
// Column means of Wo (and mean of bo)
// ---------------------------------------------------------------------------
__global__ __launch_bounds__(256) void wmean_kernel(const float* __restrict__ Wo,
                                                    const float* __restrict__ bo)
{
    __shared__ float sred[256];

    const int t    = threadIdx.x;
    const int col  = blockIdx.x * 32 + (t & 31);
    const int part = t >> 5;

    float s = 0.0f;
    const int nlo = part * 128, nhi = nlo + 128;
    for (int n = nlo; n < nhi; n++) s += Wo[(size_t)n * D + col];
    sred[t] = s;
    __syncthreads();

    if (part == 0) {
        float tot = 0.0f;
        #pragma unroll
        for (int p = 0; p < 8; p++) tot += sred[p * 32 + (t & 31)];
        d_wmean[col] = tot * (1.0f / D);
    }
    __syncthreads();

    if (blockIdx.x == 0) {
        float sb = 0.0f;
        #pragma unroll
        for (int i = t; i < D; i += 256) sb += bo[i];
        #pragma unroll
        for (int o = 16; o > 0; o >>= 1) sb += __shfl_xor_sync(0xffffffffu, sb, o);
        if ((t & 31) == 0) sred[t >> 5] = sb;
        __syncthreads();
        if (t == 0) {
            float x = 0.0f;
            #pragma unroll
            for (int p = 0; p < 8; p++) x += sred[p];
            d_bmean = x * (1.0f / D);
        }
    }
}

// ---------------------------------------------------------------------------
// Final: out[r,:] = Xt[r,:] + (Xt[r,:] . wmean + bmean)
// ---------------------------------------------------------------------------
__global__ __launch_bounds__(256) void final_kernel(float* __restrict__ out)
{
    __shared__ float red[8];
    __shared__ float bc;

    const size_t row = blockIdx.x;
    const float* x = d_Xt + row * D;
    const int t = threadIdx.x;

    float partial = 0.0f;
    #pragma unroll
    for (int dd = 0; dd < 4; dd++) {
        int idx = t + dd * 256;
        partial += x[idx] * d_wmean[idx];
    }
    #pragma unroll
    for (int o = 16; o > 0; o >>= 1) partial += __shfl_xor_sync(0xffffffffu, partial, o);
    if ((t & 31) == 0) red[t >> 5] = partial;
    __syncthreads();
    if (t < 8) {
        float s = red[t];
        #pragma unroll
        for (int o = 4; o > 0; o >>= 1) s += __shfl_xor_sync(0xffu, s, o);
        if (t == 0) bc = s + d_bmean;
    }
    __syncthreads();
    float scalar = bc;

    #pragma unroll
    for (int dd = 0; dd < 4; dd++) {
        int idx = t + dd * 256;
        out[row * D + idx] = x[idx] + scalar;
    }
}

// ---------------------------------------------------------------------------
extern "C" void kernel_launch(void* const* d_in, const int* in_sizes, int n_in,
                              void* d_out, int out_size)
{
    const float* query = (const float*)d_in[0];
    const float* key_  = (const float*)d_in[1];
    const float* value = (const float*)d_in[2];
    const int*   mask  = (const int*)  d_in[3];
    const float* Wq    = (const float*)d_in[4];
    const float* bq    = (const float*)d_in[5];
    const float* Wk    = (const float*)d_in[6];
    const float* bk    = (const float*)d_in[7];
    const float* Wv    = (const float*)d_in[8];
    const float* bv    = (const float*)d_in[9];
    const float* Wo    = (const float*)d_in[10];
    const float* bo    = (const float*)d_in[11];
    float* out = (float*)d_out;

    constexpr int FA_SMEM = 110592;
    cudaFuncSetAttribute(flash_kernel, cudaFuncAttributeMaxDynamicSharedMemorySize, FA_SMEM);

    conv_kernel<<<dim3(256, 6), 256>>>(query, key_, value, Wq, Wk, Wv);
    maskpack_kernel<<<M / 8, 256>>>(mask);

    proj_kernel<<<dim3(8, 32, 3), 256>>>(bq, bk, bv);

    wmean_kernel<<<D / 32, 256>>>(Wo, bo);

    flash_kernel<<<dim3(4, 64), 256, FA_SMEM>>>();     // mt x bh

    final_kernel<<<M, 256>>>(out);
}

// round 14
// speedup vs baseline: 7.4590x; 1.1381x over previous
#include <cuda_runtime.h>
#include <cuda_bf16.h>
#include <mma.h>
#include <cstdint>
#include <cstddef>

// Problem constants
constexpr int B  = 4;
constexpr int S  = 1024;
constexpr int D  = 1024;
constexpr int H  = 16;
constexpr int DK = 64;
constexpr int M  = B * S;          // 4096

constexpr int LDT = 72;            // smem stride for 64-wide tiles (pad 8) -> 144B rows

// Scratch (device globals; allocation-free per harness rules)
__device__ __align__(16) unsigned short g_qin[(size_t)M * D];   // bf16 inputs
__device__ __align__(16) unsigned short g_kin[(size_t)M * D];
__device__ __align__(16) unsigned short g_vin[(size_t)M * D];
__device__ __align__(16) unsigned short g_wq [(size_t)D * D];   // bf16 weights
__device__ __align__(16) unsigned short g_wk [(size_t)D * D];
__device__ __align__(16) unsigned short g_wv [(size_t)D * D];
__device__ __align__(16) unsigned short g_Qb[(size_t)M * D];    // bf16 projected
__device__ __align__(16) unsigned short g_Kb[(size_t)M * D];
__device__ __align__(16) unsigned short g_Vb[(size_t)M * D];
__device__ __align__(16) unsigned int g_mbits[(size_t)M * 32];  // packed mask bits
__device__ float d_Xt[(size_t)M * D];
__device__ float d_wmean[D];
__device__ float d_bmean;

// ---------------------------------------------------------------------------
__device__ __forceinline__ uint32_t smem_u32(const void* p) {
    uint32_t a;
    asm("{ .reg .u64 t; cvta.to.shared.u64 t, %1; cvt.u32.u64 %0, t; }" : "=r"(a) : "l"(p));
    return a;
}
#define CP_ASYNC16(dst, src) \
    asm volatile("cp.async.cg.shared.global [%0], [%1], 16;" :: "r"(dst), "l"(src) : "memory")
#define CP_COMMIT()  asm volatile("cp.async.commit_group;" ::: "memory")
#define CP_WAIT(n)   asm volatile("cp.async.wait_group %0;" :: "n"(n) : "memory")

#define LDSM_X4(r0, r1, r2, r3, a) \
    asm volatile("ldmatrix.sync.aligned.m8n8.x4.shared.b16 {%0,%1,%2,%3}, [%4];" \
                 : "=r"(r0), "=r"(r1), "=r"(r2), "=r"(r3) : "r"(a))
#define LDSM_X4_T(r0, r1, r2, r3, a) \
    asm volatile("ldmatrix.sync.aligned.m8n8.x4.trans.shared.b16 {%0,%1,%2,%3}, [%4];" \
                 : "=r"(r0), "=r"(r1), "=r"(r2), "=r"(r3) : "r"(a))
#define MMA16816(d, a0, a1, a2, a3, b0, b1) \
    asm volatile("mma.sync.aligned.m16n8k16.row.col.f32.bf16.bf16.f32 " \
                 "{%0,%1,%2,%3}, {%4,%5,%6,%7}, {%8,%9}, {%0,%1,%2,%3};" \
                 : "+f"((d)[0]), "+f"((d)[1]), "+f"((d)[2]), "+f"((d)[3]) \
                 : "r"(a0), "r"(a1), "r"(a2), "r"(a3), "r"(b0), "r"(b1))

__device__ __forceinline__ uint32_t packbf2(float lo, float hi) {
    __nv_bfloat162 p = __float22bfloat162_rn(make_float2(lo, hi));
    return *(uint32_t*)&p;
}

// ---------------------------------------------------------------------------
// fp32 -> bf16 convert pass
// ---------------------------------------------------------------------------
__global__ __launch_bounds__(256) void conv_kernel(
    const float* __restrict__ q,  const float* __restrict__ k,  const float* __restrict__ v,
    const float* __restrict__ wq, const float* __restrict__ wk, const float* __restrict__ wv)
{
    const int z = blockIdx.y;
    const float* src; unsigned short* dst; size_t n4;
    switch (z) {
        case 0: src = q;  dst = g_qin; n4 = (size_t)M * D / 4; break;
        case 1: src = k;  dst = g_kin; n4 = (size_t)M * D / 4; break;
        case 2: src = v;  dst = g_vin; n4 = (size_t)M * D / 4; break;
        case 3: src = wq; dst = g_wq;  n4 = (size_t)D * D / 4; break;
        case 4: src = wk; dst = g_wk;  n4 = (size_t)D * D / 4; break;
        default: src = wv; dst = g_wv; n4 = (size_t)D * D / 4; break;
    }
    for (size_t i = (size_t)blockIdx.x * 256 + threadIdx.x; i < n4;
         i += (size_t)gridDim.x * 256) {
        float4 f = ((const float4*)src)[i];
        uint2 o;
        o.x = packbf2(f.x, f.y);
        o.y = packbf2(f.z, f.w);
        ((uint2*)dst)[i] = o;
    }
}

// ---------------------------------------------------------------------------
// Pack mask int32 -> bits. One warp per global row.
// ---------------------------------------------------------------------------
__global__ __launch_bounds__(256) void maskpack_kernel(const int* __restrict__ mask)
{
    const int row  = blockIdx.x * 8 + (threadIdx.x >> 5);
    const int lane = threadIdx.x & 31;
    const int* src = mask + (size_t)row * 1024;
    #pragma unroll
    for (int w = 0; w < 32; w++) {
        int v = src[w * 32 + lane];
        uint32_t bits = __ballot_sync(0xffffffffu, v != 0);
        if (lane == 0) g_mbits[(size_t)row * 32 + w] = bits;
    }
}

// ---------------------------------------------------------------------------
// Fused QKV projection, raw mma.sync. Grid (8, 32, 3), 256 thr (8 warps).
// CTA tile 128(m) x 128(n), BK=64, 2-stage cp.async.
// Warp grid 2x4; warp tile 64x32 = 4 m16-blocks x 4 n8-tiles.
// B-fragment consumption mirrors the verified flash pattern:
//   one x4 load at (8 n-rows, 32 k-cols) -> regs {0,1} = kstep lo, {2,3} = kstep hi.
// Epilogue: bias in regs, direct packed-bf16 stores (no smem patch).
// Dynamic smem: 2 stages x (A 18432 + B 18432) = 73728 B -> 2 CTAs/SM.
// ---------------------------------------------------------------------------
extern __shared__ char dyn_smem[];

__global__ __launch_bounds__(256, 2) void proj_kernel(
    const float* __restrict__ bq, const float* __restrict__ bk,
    const float* __restrict__ bv)
{
    const uint32_t uS = smem_u32(dyn_smem);
    constexpr uint32_t TILEB  = 128 * LDT * 2;   // 18432
    constexpr uint32_t STAGEB = 2 * TILEB;       // A+B per stage

    const int t = threadIdx.x, wid = t >> 5, lane = t & 31;
    const int m0 = blockIdx.y * 128, n0 = blockIdx.x * 128;
    const int z  = blockIdx.z;
    const int wm = wid >> 2, wn = wid & 3;       // 2 x 4 warps
    const int g = lane >> 2, qtid = lane & 3;

    // ldmatrix lane patterns
    const int x4row = (lane & 7) + ((lane >> 3) & 1) * 8;   // A (row-major, m16)
    const int x4col = (lane >> 4) * 8;
    const int krow  = lane & 7;                              // B (8 n-rows x 32 k)
    const int kcol  = (lane >> 3) * 8;

    const unsigned short* Ain; const unsigned short* Wb;
    const float* bias; unsigned short* dst;
    switch (z) {
        case 0: Ain = g_qin; Wb = g_wq; bias = bq; dst = g_Qb; break;
        case 1: Ain = g_kin; Wb = g_wk; bias = bk; dst = g_Kb; break;
        default: Ain = g_vin; Wb = g_wv; bias = bv; dst = g_Vb; break;
    }
    const unsigned short* Asrc = Ain + (size_t)m0 * 1024;
    const unsigned short* Wsrc = Wb  + (size_t)n0 * 1024;

    auto stage = [&](int k0, int buf) {
        const uint32_t uA = uS + buf * STAGEB;
        const uint32_t uB = uA + TILEB;
        #pragma unroll
        for (int i = t; i < 1024; i += 256) {
            int r = i >> 3, q = i & 7;
            CP_ASYNC16(uA + (uint32_t)(r * LDT + q * 8) * 2,
                       Asrc + (size_t)r * 1024 + k0 + q * 8);
        }
        #pragma unroll
        for (int i = t; i < 1024; i += 256) {
            int r = i >> 3, q = i & 7;
            CP_ASYNC16(uB + (uint32_t)(r * LDT + q * 8) * 2,
                       Wsrc + (size_t)r * 1024 + k0 + q * 8);
        }
        CP_COMMIT();
    };

    float acc[4][4][4];                          // [m-block][n8-tile][frag]
    #pragma unroll
    for (int mb = 0; mb < 4; mb++)
        #pragma unroll
        for (int nt = 0; nt < 4; nt++)
            #pragma unroll
            for (int c = 0; c < 4; c++) acc[mb][nt][c] = 0.0f;

    stage(0, 0);

    for (int k0 = 0; k0 < 1024; k0 += 64) {
        const int buf = (k0 >> 6) & 1;
        if (k0 + 64 < 1024) { stage(k0 + 64, buf ^ 1); CP_WAIT(1); }
        else                { CP_WAIT(0); }
        __syncthreads();

        const uint32_t uA = uS + buf * STAGEB;
        const uint32_t uB = uA + TILEB;

        #pragma unroll
        for (int kc = 0; kc < 2; kc++) {         // two k32 chunks within BK=64
            // B frags: [n8-tile][x4 regs]; tile nt covers n-rows wn*32 + nt*8,
            // x4 load spans k = kc*32 .. kc*32+32 for those 8 rows.
            uint32_t kb[4][4];
            #pragma unroll
            for (int nt = 0; nt < 4; nt++) {
                uint32_t addr = uB + (uint32_t)((wn * 32 + nt * 8 + krow) * LDT
                                                + kc * 32 + kcol) * 2;
                LDSM_X4(kb[nt][0], kb[nt][1], kb[nt][2], kb[nt][3], addr);
            }
            #pragma unroll
            for (int ks2 = 0; ks2 < 2; ks2++) {  // k16 step within chunk
                const int ks = kc * 2 + ks2;
                uint32_t a[4][4];
                #pragma unroll
                for (int mb = 0; mb < 4; mb++) {
                    uint32_t addr = uA + (uint32_t)((wm * 64 + mb * 16 + x4row) * LDT
                                                    + ks * 16 + x4col) * 2;
                    LDSM_X4(a[mb][0], a[mb][1], a[mb][2], a[mb][3], addr);
                }
                #pragma unroll
                for (int mb = 0; mb < 4; mb++)
                    #pragma unroll
                    for (int nt = 0; nt < 4; nt++)
                        MMA16816(acc[mb][nt],
                                 a[mb][0], a[mb][1], a[mb][2], a[mb][3],
                                 kb[nt][2 * ks2], kb[nt][2 * ks2 + 1]);
            }
        }
        __syncthreads();
    }

    // epilogue: bias + direct packed-bf16 stores
    float2 bv2[4];
    #pragma unroll
    for (int nt = 0; nt < 4; nt++) {
        int n = n0 + wn * 32 + nt * 8 + qtid * 2;
        bv2[nt] = *(const float2*)&bias[n];
    }
    #pragma unroll
    for (int mb = 0; mb < 4; mb++) {
        const int r0 = m0 + wm * 64 + mb * 16 + g;
        #pragma unroll
        for (int nt = 0; nt < 4; nt++) {
            int n = n0 + wn * 32 + nt * 8 + qtid * 2;
            *(uint32_t*)&dst[(size_t)r0 * 1024 + n] =
                packbf2(acc[mb][nt][0] + bv2[nt].x, acc[mb][nt][1] + bv2[nt].y);
            *(uint32_t*)&dst[(size_t)(r0 + 8) * 1024 + n] =
                packbf2(acc[mb][nt][2] + bv2[nt].x, acc[mb][nt][3] + bv2[nt].y);
        }
    }
}

// ---------------------------------------------------------------------------
// Flash attention v2, 32 q-rows per warp (unchanged, verified). Grid (4, 64).
// smem: sQ 0..36864 | sK (2 bufs) ..73728 | sV (2 bufs) ..110592
// ---------------------------------------------------------------------------
__global__ __launch_bounds__(256) void flash_kernel()
{
    const uint32_t uQ  = smem_u32(dyn_smem);
    const uint32_t uK0 = uQ + 36864;
    const uint32_t uV0 = uQ + 73728;
    constexpr uint32_t TILEB = 18432;

    const int t = threadIdx.x, wid = t >> 5, lane = t & 31;
    const int mt = blockIdx.x, bh = blockIdx.y;
    const int b = bh >> 4, h = bh & 15;
    const int g = lane >> 2, qtid = lane & 3;
    const int qrow0 = mt * 256;

    const int x4row = (lane & 7) + ((lane >> 3) & 1) * 8;
    const int x4col = (lane >> 4) * 8;
    const int krow  = lane & 7;
    const int kcol  = (lane >> 3) * 8;

    const unsigned short* Ksrc = g_Kb + ((size_t)(b * 1024)) * 1024 + h * 64;
    const unsigned short* Vsrc = g_Vb + ((size_t)(b * 1024)) * 1024 + h * 64;

    auto stage = [&](int kt, int buf) {
        const unsigned short* ks = Ksrc + (size_t)(kt * 128) * 1024;
        const unsigned short* vs = Vsrc + (size_t)(kt * 128) * 1024;
        #pragma unroll
        for (int i = t; i < 1024; i += 256) {
            int r = i >> 3, q = i & 7;
            CP_ASYNC16(uK0 + buf * TILEB + (uint32_t)(r * LDT + q * 8) * 2,
                       ks + (size_t)r * 1024 + q * 8);
        }
        #pragma unroll
        for (int i = t; i < 1024; i += 256) {
            int r = i >> 3, q = i & 7;
            CP_ASYNC16(uV0 + buf * TILEB + (uint32_t)(r * LDT + q * 8) * 2,
                       vs + (size_t)r * 1024 + q * 8);
        }
        CP_COMMIT();
    };

    stage(0, 0);

    const unsigned short* Qsrc = g_Qb + ((size_t)(b * 1024 + qrow0)) * 1024 + h * 64;
    #pragma unroll
    for (int i = t; i < 2048; i += 256) {
        int r = i >> 3, q = i & 7;
        uint4 v = *(const uint4*)(Qsrc + (size_t)r * 1024 + q * 8);
        uint32_t a = uQ + (uint32_t)(r * LDT + q * 8) * 2;
        asm volatile("st.shared.v4.b32 [%0], {%1,%2,%3,%4};"
                     :: "r"(a), "r"(v.x), "r"(v.y), "r"(v.z), "r"(v.w) : "memory");
    }
    __syncthreads();

    uint32_t qa[2][4][4];
    #pragma unroll
    for (int r = 0; r < 2; r++)
        #pragma unroll
        for (int ks = 0; ks < 4; ks++) {
            uint32_t a = uQ + (uint32_t)((wid * 32 + r * 16 + x4row) * LDT + ks * 16 + x4col) * 2;
            LDSM_X4(qa[r][ks][0], qa[r][ks][1], qa[r][ks][2], qa[r][ks][3], a);
        }

    float oacc[2][8][4];
    #pragma unroll
    for (int r = 0; r < 2; r++)
        #pragma unroll
        for (int n = 0; n < 8; n++)
            #pragma unroll
            for (int c = 0; c < 4; c++) oacc[r][n][c] = 0.0f;

    float lsum[2][2] = {{0, 0}, {0, 0}};

    const int rg0 = b * 1024 + qrow0 + wid * 32 + g;
    const uint4* mb = (const uint4*)g_mbits;

    for (int kt = 0; kt < 8; kt++) {
        const int buf = kt & 1;
        if (kt < 7) { stage(kt + 1, buf ^ 1); CP_WAIT(1); }
        else        { CP_WAIT(0); }
        __syncthreads();

        const uint32_t uK = uK0 + buf * TILEB;
        const uint32_t uV = uV0 + buf * TILEB;

        uint4 mw[4];
        mw[0] = mb[(size_t)rg0 * 8 + kt];
        mw[1] = mb[(size_t)(rg0 + 8) * 8 + kt];
        mw[2] = mb[(size_t)(rg0 + 16) * 8 + kt];
        mw[3] = mb[(size_t)(rg0 + 24) * 8 + kt];

        #pragma unroll
        for (int jp = 0; jp < 8; jp++) {
            float s00[4] = {0, 0, 0, 0};
            float s01[4] = {0, 0, 0, 0};
            float s10[4] = {0, 0, 0, 0};
            float s11[4] = {0, 0, 0, 0};

            {
                uint32_t k0, k1, k2, k3;
                uint32_t a0 = uK + (uint32_t)((jp * 16 + krow) * LDT + kcol) * 2;
                LDSM_X4(k0, k1, k2, k3, a0);
                MMA16816(s00, qa[0][0][0], qa[0][0][1], qa[0][0][2], qa[0][0][3], k0, k1);
                MMA16816(s00, qa[0][1][0], qa[0][1][1], qa[0][1][2], qa[0][1][3], k2, k3);
                MMA16816(s01, qa[1][0][0], qa[1][0][1], qa[1][0][2], qa[1][0][3], k0, k1);
                MMA16816(s01, qa[1][1][0], qa[1][1][1], qa[1][1][2], qa[1][1][3], k2, k3);
                uint32_t a1 = uK + (uint32_t)((jp * 16 + krow) * LDT + 32 + kcol) * 2;
                LDSM_X4(k0, k1, k2, k3, a1);
                MMA16816(s00, qa[0][2][0], qa[0][2][1], qa[0][2][2], qa[0][2][3], k0, k1);
                MMA16816(s00, qa[0][3][0], qa[0][3][1], qa[0][3][2], qa[0][3][3], k2, k3);
                MMA16816(s01, qa[1][2][0], qa[1][2][1], qa[1][2][2], qa[1][2][3], k0, k1);
                MMA16816(s01, qa[1][3][0], qa[1][3][1], qa[1][3][2], qa[1][3][3], k2, k3);
                uint32_t a2 = uK + (uint32_t)((jp * 16 + 8 + krow) * LDT + kcol) * 2;
                LDSM_X4(k0, k1, k2, k3, a2);
                MMA16816(s10, qa[0][0][0], qa[0][0][1], qa[0][0][2], qa[0][0][3], k0, k1);
                MMA16816(s10, qa[0][1][0], qa[0][1][1], qa[0][1][2], qa[0][1][3], k2, k3);
                MMA16816(s11, qa[1][0][0], qa[1][0][1], qa[1][0][2], qa[1][0][3], k0, k1);
                MMA16816(s11, qa[1][1][0], qa[1][1][1], qa[1][1][2], qa[1][1][3], k2, k3);
                uint32_t a3 = uK + (uint32_t)((jp * 16 + 8 + krow) * LDT + 32 + kcol) * 2;
                LDSM_X4(k0, k1, k2, k3, a3);
                MMA16816(s10, qa[0][2][0], qa[0][2][1], qa[0][2][2], qa[0][2][3], k0, k1);
                MMA16816(s10, qa[0][3][0], qa[0][3][1], qa[0][3][2], qa[0][3][3], k2, k3);
                MMA16816(s11, qa[1][2][0], qa[1][2][1], qa[1][2][2], qa[1][2][3], k0, k1);
                MMA16816(s11, qa[1][3][0], qa[1][3][1], qa[1][3][2], qa[1][3][3], k2, k3);
            }

            const int sft = (jp & 1) * 16 + qtid * 2;
            uint32_t pa[2][4];

            #pragma unroll
            for (int r = 0; r < 2; r++) {
                uint32_t wA = (&mw[2 * r].x)[jp >> 1];
                uint32_t wB = (&mw[2 * r + 1].x)[jp >> 1];
                float* t0 = (r == 0) ? s00 : s01;
                float* t1 = (r == 0) ? s10 : s11;

                float e00 = ((wA >> sft)       & 1) ? t0[0] * 0.125f : -1e9f;
                float e01 = ((wA >> (sft + 1)) & 1) ? t0[1] * 0.125f : -1e9f;
                float e02 = ((wB >> sft)       & 1) ? t0[2] * 0.125f : -1e9f;
                float e03 = ((wB >> (sft + 1)) & 1) ? t0[3] * 0.125f : -1e9f;
                float e10 = ((wA >> (sft + 8)) & 1) ? t1[0] * 0.125f : -1e9f;
                float e11 = ((wA >> (sft + 9)) & 1) ? t1[1] * 0.125f : -1e9f;
                float e12 = ((wB >> (sft + 8)) & 1) ? t1[2] * 0.125f : -1e9f;
                float e13 = ((wB >> (sft + 9)) & 1) ? t1[3] * 0.125f : -1e9f;

                e00 = __expf(fmaxf(e00, -30.0f)); e01 = __expf(fmaxf(e01, -30.0f));
                e02 = __expf(fmaxf(e02, -30.0f)); e03 = __expf(fmaxf(e03, -30.0f));
                e10 = __expf(fmaxf(e10, -30.0f)); e11 = __expf(fmaxf(e11, -30.0f));
                e12 = __expf(fmaxf(e12, -30.0f)); e13 = __expf(fmaxf(e13, -30.0f));

                lsum[r][0] += e00 + e01 + e10 + e11;
                lsum[r][1] += e02 + e03 + e12 + e13;

                pa[r][0] = packbf2(e00, e01);
                pa[r][1] = packbf2(e02, e03);
                pa[r][2] = packbf2(e10, e11);
                pa[r][3] = packbf2(e12, e13);
            }

            #pragma unroll
            for (int dkp = 0; dkp < 4; dkp++) {
                uint32_t v0, v1, v2, v3;
                uint32_t a = uV + (uint32_t)((jp * 16 + x4row) * LDT + dkp * 16 + x4col) * 2;
                LDSM_X4_T(v0, v1, v2, v3, a);
                MMA16816(oacc[0][2 * dkp],     pa[0][0], pa[0][1], pa[0][2], pa[0][3], v0, v1);
                MMA16816(oacc[0][2 * dkp + 1], pa[0][0], pa[0][1], pa[0][2], pa[0][3], v2, v3);
                MMA16816(oacc[1][2 * dkp],     pa[1][0], pa[1][1], pa[1][2], pa[1][3], v0, v1);
                MMA16816(oacc[1][2 * dkp + 1], pa[1][0], pa[1][1], pa[1][2], pa[1][3], v2, v3);
            }
        }
        __syncthreads();
    }

    #pragma unroll
    for (int r = 0; r < 2; r++)
        #pragma unroll
        for (int o = 1; o < 4; o <<= 1) {
            lsum[r][0] += __shfl_xor_sync(0xffffffffu, lsum[r][0], o);
            lsum[r][1] += __shfl_xor_sync(0xffffffffu, lsum[r][1], o);
        }

    #pragma unroll
    for (int r = 0; r < 2; r++) {
        const float inv0 = 1.0f / lsum[r][0], inv1 = 1.0f / lsum[r][1];
        const size_t row0 = (size_t)rg0 + 16 * r;
        #pragma unroll
        for (int n = 0; n < 8; n++) {
            int col = h * 64 + n * 8 + qtid * 2;
            float v0 = oacc[r][n][0] * inv0, v1 = oacc[r][n][1] * inv0;
            float v2 = oacc[r][n][2] * inv1, v3 = oacc[r][n][3] * inv1;
            v0 = (v0 > 0.2f) ? v0 : 0.0f;
            v1 = (v1 > 0.2f) ? v1 : 0.0f;
            v2 = (v2 > 0.2f) ? v2 : 0.0f;
            v3 = (v3 > 0.2f) ? v3 : 0.0f;
            *(float2*)&d_Xt[row0 * 1024 + col]       = make_float2(v0, v1);
            *(float2*)&d_Xt[(row0 + 8) * 1024 + col] = make_float2(v2, v3);
        }
    }
}

// ---------------------------------------------------------------------------
// Column means of Wo (and mean of bo)
// ---------------------------------------------------------------------------
__global__ __launch_bounds__(256) void wmean_kernel(const float* __restrict__ Wo,
                                                    const float* __restrict__ bo)
{
    __shared__ float sred[256];

    const int t    = threadIdx.x;
    const int col  = blockIdx.x * 32 + (t & 31);
    const int part = t >> 5;

    float s = 0.0f;
    const int nlo = part * 128, nhi = nlo + 128;
    for (int n = nlo; n < nhi; n++) s += Wo[(size_t)n * D + col];
    sred[t] = s;
    __syncthreads();

    if (part == 0) {
        float tot = 0.0f;
        #pragma unroll
        for (int p = 0; p < 8; p++) tot += sred[p * 32 + (t & 31)];
        d_wmean[col] = tot * (1.0f / D);
    }
    __syncthreads();

    if (blockIdx.x == 0) {
        float sb = 0.0f;
        #pragma unroll
        for (int i = t; i < D; i += 256) sb += bo[i];
        #pragma unroll
        for (int o = 16; o > 0; o >>= 1) sb += __shfl_xor_sync(0xffffffffu, sb, o);
        if ((t & 31) == 0) sred[t >> 5] = sb;
        __syncthreads();
        if (t == 0) {
            float x = 0.0f;
            #pragma unroll
            for (int p = 0; p < 8; p++) x += sred[p];
            d_bmean = x * (1.0f / D);
        }
    }
}

// ---------------------------------------------------------------------------
// Final: out[r,:] = Xt[r,:] + (Xt[r,:] . wmean + bmean)  -- float4 vectorized
// ---------------------------------------------------------------------------
__global__ __launch_bounds__(256) void final_kernel(float* __restrict__ out)
{
    __shared__ float red[8];
    __shared__ float bc;

    const size_t row = blockIdx.x;
    const int t = threadIdx.x;

    float4 x4 = *(const float4*)(d_Xt + row * D + t * 4);
    float4 w4 = *(const float4*)(d_wmean + t * 4);

    float partial = x4.x * w4.x + x4.y * w4.y + x4.z * w4.z + x4.w * w4.w;
    #pragma unroll
    for (int o = 16; o > 0; o >>= 1) partial += __shfl_xor_sync(0xffffffffu, partial, o);
    if ((t & 31) == 0) red[t >> 5] = partial;
    __syncthreads();
    if (t < 8) {
        float s = red[t];
        #pragma unroll
        for (int o = 4; o > 0; o >>= 1) s += __shfl_xor_sync(0xffu, s, o);
        if (t == 0) bc = s + d_bmean;
    }
    __syncthreads();
    const float scalar = bc;

    float4 o4;
    o4.x = x4.x + scalar; o4.y = x4.y + scalar;
    o4.z = x4.z + scalar; o4.w = x4.w + scalar;
    *(float4*)(out + row * D + t * 4) = o4;
}

// ---------------------------------------------------------------------------
extern "C" void kernel_launch(void* const* d_in, const int* in_sizes, int n_in,
                              void* d_out, int out_size)
{
    const float* query = (const float*)d_in[0];
    const float* key_  = (const float*)d_in[1];
    const float* value = (const float*)d_in[2];
    const int*   mask  = (const int*)  d_in[3];
    const float* Wq    = (const float*)d_in[4];
    const float* bq    = (const float*)d_in[5];
    const float* Wk    = (const float*)d_in[6];
    const float* bk    = (const float*)d_in[7];
    const float* Wv    = (const float*)d_in[8];
    const float* bv    = (const float*)d_in[9];
    const float* Wo    = (const float*)d_in[10];
    const float* bo    = (const float*)d_in[11];
    float* out = (float*)d_out;

    constexpr int PROJ_SMEM = 73728;
    constexpr int FA_SMEM   = 110592;
    cudaFuncSetAttribute(proj_kernel,  cudaFuncAttributeMaxDynamicSharedMemorySize, PROJ_SMEM);
    cudaFuncSetAttribute(flash_kernel, cudaFuncAttributeMaxDynamicSharedMemorySize, FA_SMEM);

    conv_kernel<<<dim3(256, 6), 256>>>(query, key_, value, Wq, Wk, Wv);
    maskpack_kernel<<<M / 8, 256>>>(mask);

    proj_kernel<<<dim3(8, 32, 3), 256, PROJ_SMEM>>>(bq, bk, bv);

    wmean_kernel<<<D / 32, 256>>>(Wo, bo);

    flash_kernel<<<dim3(4, 64), 256, FA_SMEM>>>();     // mt x bh

    final_kernel<<<M, 256>>>(out);
}